// round 6
// baseline (speedup 1.0000x reference)
#include <cuda_runtime.h>
#include <math.h>

#define CB 2
#define CT 2048
#define CD 1024
#define CH 16
#define CBT 4096            // B*T
#define QKVLD 3072
#define NBH 32              // B*H
#define NCH 16              // chunks over T
#define CLEN 128            // chunk length

// ---------------- scratch (device globals; no runtime allocation) ----------------
__device__ float g_qkv[(size_t)CBT * QKVLD];
__device__ float g_seqout[(size_t)CBT * CD];
__device__ float g_z[(size_t)CBT * CD];
__device__ float g_P[(size_t)CBT * 272];      // [w1|w2|r1|r2|gate_pre]
__device__ float g_smallW[(size_t)CD * 272];
__device__ float g_Jw[NBH * CT * 6];
__device__ float g_Jr[NBH * CT * 6];
__device__ float g_rd[NBH * CT * 6];
__device__ float g_intraw[NBH * CT];
__device__ float g_intrar[NBH * CT];
__device__ float g_L[NBH * NCH * 42];
__device__ float g_Ms[NBH * NCH * 42];
__device__ float g_score[NBH * CT];
__device__ float g_gated[CBT];

__device__ __forceinline__ float sigf(float x) { return 1.f / (1.f + __expf(-x)); }

// ---------------- concat small weights into [1024 x 272] ----------------
__global__ void rw_concat_w(const float* __restrict__ w1w, const float* __restrict__ w2w,
                            const float* __restrict__ w1r, const float* __restrict__ w2r,
                            const float* __restrict__ memg) {
    int i = blockIdx.x * 256 + threadIdx.x;
    if (i >= CD * 272) return;
    int k = i / 272, n = i % 272;
    float v;
    if (n < 64)       v = w1w[k * 64 + n];
    else if (n < 128) v = w2w[k * 64 + (n - 64)];
    else if (n < 192) v = w1r[k * 64 + (n - 128)];
    else if (n < 256) v = w2r[k * 64 + (n - 192)];
    else              v = memg[k * 16 + (n - 256)];
    g_smallW[i] = v;
}

// ---------------- fp32 GEMM: C[M,N] = A[M,1024] @ W[1024,N] (+bias) ----------------
// mode=1: C = seqout + gated[m] * (acc + bias)
__global__ __launch_bounds__(256) void rw_gemm(
    const float* __restrict__ A, int lda,
    const float* __restrict__ W, int ldw,
    const float* __restrict__ bias,
    float* __restrict__ C, int ldc, int N,
    int mode, const float* __restrict__ seqout, const float* __restrict__ gated) {
    __shared__ float As[16][132];
    __shared__ float Bs[16][68];
    const int tid = threadIdx.x;
    const int tx = tid & 15, ty = tid >> 4;
    const int m0 = blockIdx.y * 128;
    const int n0 = blockIdx.x * 64;

    float acc[8][4];
#pragma unroll
    for (int i = 0; i < 8; i++)
#pragma unroll
        for (int j = 0; j < 4; j++) acc[i][j] = 0.f;

    for (int k0 = 0; k0 < CD; k0 += 16) {
#pragma unroll
        for (int u = 0; u < 2; u++) {
            int idx = tid + u * 256;
            int row = idx >> 2;
            int kk = (idx & 3) << 2;
            float4 v = *(const float4*)(A + (size_t)(m0 + row) * lda + k0 + kk);
            As[kk + 0][row] = v.x; As[kk + 1][row] = v.y;
            As[kk + 2][row] = v.z; As[kk + 3][row] = v.w;
        }
        {
            int kk = tid >> 4;
            int j = (tid & 15) << 2;
            float4 v = make_float4(0.f, 0.f, 0.f, 0.f);
            if (n0 + j < N) v = *(const float4*)(W + (size_t)(k0 + kk) * ldw + n0 + j);
            *(float4*)&Bs[kk][j] = v;
        }
        __syncthreads();
#pragma unroll
        for (int kk = 0; kk < 16; kk++) {
            float4 a0 = *(const float4*)&As[kk][ty * 8];
            float4 a1 = *(const float4*)&As[kk][ty * 8 + 4];
            float4 b  = *(const float4*)&Bs[kk][tx * 4];
            float av[8] = {a0.x, a0.y, a0.z, a0.w, a1.x, a1.y, a1.z, a1.w};
            float bv[4] = {b.x, b.y, b.z, b.w};
#pragma unroll
            for (int i = 0; i < 8; i++)
#pragma unroll
                for (int j = 0; j < 4; j++) acc[i][j] += av[i] * bv[j];
        }
        __syncthreads();
    }
#pragma unroll
    for (int i = 0; i < 8; i++) {
        int m = m0 + ty * 8 + i;
#pragma unroll
        for (int j = 0; j < 4; j++) {
            int n = n0 + tx * 4 + j;
            if (n < N) {
                float v = acc[i][j];
                if (bias) v += bias[n];
                if (mode) v = seqout[(size_t)m * CD + n] + gated[m] * v;
                C[(size_t)m * ldc + n] = v;
            }
        }
    }
}

// ---------------- flash attention, 64q x 64k tiles, DH=64 ----------------
#define SWK(d, c) ((c) ^ ((((d) >> 2) & 7) << 2))
#define SWP(q, c) ((c) ^ (((q) & 7) << 2))

__global__ __launch_bounds__(256) void rw_attn() {
    __shared__ float Qs[64][64];   // [d][q] swizzled, pre-scaled
    __shared__ float KP[64][64];   // K as [d][k] swizzled; reused as P [q][k] swizzled
    __shared__ float Vs[64][64];   // [k][d]
    const int tid = threadIdx.x;
    const int tx = tid & 15, ty = tid >> 4;
    const int qi = blockIdx.x;
    const int b = blockIdx.y >> 4, h = blockIdx.y & 15;

#pragma unroll
    for (int u = 0; u < 4; u++) {
        int idx = tid + u * 256;
        int r = idx >> 4;
        int dd = (idx & 15) << 2;
        const float* p = g_qkv + (size_t)(b * CT + qi * 64 + r) * QKVLD + h * 64 + dd;
        float4 v = *(const float4*)p;
        Qs[dd + 0][SWK(dd + 0, r)] = v.x * 0.125f;
        Qs[dd + 1][SWK(dd + 1, r)] = v.y * 0.125f;
        Qs[dd + 2][SWK(dd + 2, r)] = v.z * 0.125f;
        Qs[dd + 3][SWK(dd + 3, r)] = v.w * 0.125f;
    }

    float O[4][4], mi[4], li[4];
#pragma unroll
    for (int i = 0; i < 4; i++) {
        mi[i] = -1e30f; li[i] = 0.f;
#pragma unroll
        for (int j = 0; j < 4; j++) O[i][j] = 0.f;
    }

    for (int j = 0; j <= qi; j++) {
        __syncthreads();
#pragma unroll
        for (int u = 0; u < 4; u++) {
            int idx = tid + u * 256;
            int r = idx >> 4;
            int dd = (idx & 15) << 2;
            const float* kp = g_qkv + (size_t)(b * CT + j * 64 + r) * QKVLD + CD + h * 64 + dd;
            float4 kv = *(const float4*)kp;
            KP[dd + 0][SWK(dd + 0, r)] = kv.x;
            KP[dd + 1][SWK(dd + 1, r)] = kv.y;
            KP[dd + 2][SWK(dd + 2, r)] = kv.z;
            KP[dd + 3][SWK(dd + 3, r)] = kv.w;
            float4 vv = *(const float4*)(kp + CD);
            *(float4*)&Vs[r][dd] = vv;
        }
        __syncthreads();

        float s[4][4];
#pragma unroll
        for (int i = 0; i < 4; i++)
#pragma unroll
            for (int jj = 0; jj < 4; jj++) s[i][jj] = 0.f;
#pragma unroll 8
        for (int d = 0; d < 64; d++) {
            float4 a  = *(const float4*)&Qs[d][SWK(d, ty * 4)];
            float4 bb = *(const float4*)&KP[d][SWK(d, tx * 4)];
            float av[4] = {a.x, a.y, a.z, a.w};
            float bv[4] = {bb.x, bb.y, bb.z, bb.w};
#pragma unroll
            for (int i = 0; i < 4; i++)
#pragma unroll
                for (int jj = 0; jj < 4; jj++) s[i][jj] += av[i] * bv[jj];
        }
        __syncthreads();   // done reading K, KP can become P

        if (j == qi) {
#pragma unroll
            for (int i = 0; i < 4; i++)
#pragma unroll
                for (int jj = 0; jj < 4; jj++)
                    if (tx * 4 + jj > ty * 4 + i) s[i][jj] = -1e30f;
        }

#pragma unroll
        for (int i = 0; i < 4; i++) {
            float mloc = fmaxf(fmaxf(s[i][0], s[i][1]), fmaxf(s[i][2], s[i][3]));
#pragma unroll
            for (int msk = 8; msk; msk >>= 1)
                mloc = fmaxf(mloc, __shfl_xor_sync(0xffffffffu, mloc, msk));
            float mnew = fmaxf(mi[i], mloc);
            float corr = __expf(mi[i] - mnew);
            mi[i] = mnew;
            float p0 = __expf(s[i][0] - mnew);
            float p1 = __expf(s[i][1] - mnew);
            float p2 = __expf(s[i][2] - mnew);
            float p3 = __expf(s[i][3] - mnew);
            float lsum = p0 + p1 + p2 + p3;
#pragma unroll
            for (int msk = 8; msk; msk >>= 1)
                lsum += __shfl_xor_sync(0xffffffffu, lsum, msk);
            li[i] = li[i] * corr + lsum;
#pragma unroll
            for (int jj = 0; jj < 4; jj++) O[i][jj] *= corr;
            int q = ty * 4 + i;
            *(float4*)&KP[q][SWP(q, tx * 4)] = make_float4(p0, p1, p2, p3);
        }
        __syncthreads();

#pragma unroll 8
        for (int k = 0; k < 64; k++) {
            float4 vv = *(const float4*)&Vs[k][tx * 4];
            float vb[4] = {vv.x, vv.y, vv.z, vv.w};
            float pw[4];
#pragma unroll
            for (int i = 0; i < 4; i++) pw[i] = KP[ty * 4 + i][SWP(ty * 4 + i, k)];
#pragma unroll
            for (int i = 0; i < 4; i++)
#pragma unroll
                for (int jj = 0; jj < 4; jj++) O[i][jj] += pw[i] * vb[jj];
        }
    }

#pragma unroll
    for (int i = 0; i < 4; i++) {
        float inv = 1.f / li[i];
        float4 o = make_float4(O[i][0] * inv, O[i][1] * inv, O[i][2] * inv, O[i][3] * inv);
        *(float4*)(g_seqout + (size_t)(b * CT + qi * 64 + ty * 4 + i) * CD + h * 64 + tx * 4) = o;
    }
}

// ---------------- Plucker lines ----------------
__global__ __launch_bounds__(256) void rw_lines() {
    int idx = blockIdx.x * 256 + threadIdx.x;
    if (idx >= CBT * CH) return;
    int h = idx & 15, bt = idx >> 4;
    int b = bt >> 11, t = bt & (CT - 1);
    const float* Pr = g_P + (size_t)bt * 272;
    float w1[4] = {0.f, 0.f, 0.f, 0.f}, w2[4], r1[4], r2[4];
    if (t > 0) {
        const float* Pp = g_P + (size_t)(bt - 1) * 272;
#pragma unroll
        for (int k = 0; k < 4; k++) w1[k] = Pp[h * 4 + k];
    }
#pragma unroll
    for (int k = 0; k < 4; k++) {
        w2[k] = Pr[64 + h * 4 + k];
        r1[k] = Pr[128 + h * 4 + k];
        r2[k] = Pr[192 + h * 4 + k];
    }
    float Lw[6], Lr[6];
    Lw[0] = w1[0]*w2[1] - w1[1]*w2[0];
    Lw[1] = w1[0]*w2[2] - w1[2]*w2[0];
    Lw[2] = w1[0]*w2[3] - w1[3]*w2[0];
    Lw[3] = w1[1]*w2[2] - w1[2]*w2[1];
    Lw[4] = w1[1]*w2[3] - w1[3]*w2[1];
    Lw[5] = w1[2]*w2[3] - w1[3]*w2[2];
    Lr[0] = r1[0]*r2[1] - r1[1]*r2[0];
    Lr[1] = r1[0]*r2[2] - r1[2]*r2[0];
    Lr[2] = r1[0]*r2[3] - r1[3]*r2[0];
    Lr[3] = r1[1]*r2[2] - r1[2]*r2[1];
    Lr[4] = r1[1]*r2[3] - r1[3]*r2[1];
    Lr[5] = r1[2]*r2[3] - r1[3]*r2[2];
    float nw = 0.f, nr = 0.f;
#pragma unroll
    for (int k = 0; k < 6; k++) { nw += Lw[k]*Lw[k]; nr += Lr[k]*Lr[k]; }
    float iw = 1.f / fmaxf(sqrtf(nw), 1e-12f);
    float ir = 1.f / fmaxf(sqrtf(nr), 1e-12f);
#pragma unroll
    for (int k = 0; k < 6; k++) { Lw[k] *= iw; Lr[k] *= ir; }
    int bh = b * CH + h;
    size_t base = ((size_t)bh * CT + t) * 6;
    // Jv = (v5, -v4, v3, v2, -v1, v0)
    g_Jw[base+0] =  Lw[5]; g_Jw[base+1] = -Lw[4]; g_Jw[base+2] = Lw[3];
    g_Jw[base+3] =  Lw[2]; g_Jw[base+4] = -Lw[1]; g_Jw[base+5] = Lw[0];
    g_Jr[base+0] =  Lr[5]; g_Jr[base+1] = -Lr[4]; g_Jr[base+2] = Lr[3];
    g_Jr[base+3] =  Lr[2]; g_Jr[base+4] = -Lr[1]; g_Jr[base+5] = Lr[0];
#pragma unroll
    for (int k = 0; k < 6; k++) g_rd[base + k] = Lr[k];
}

// ---------------- scan A: intra-chunk scores + local 6x6 sym matrices ----------------
__global__ __launch_bounds__(128) void rw_scanA(const float* __restrict__ decay_logits) {
    const int bh = blockIdx.x, c = blockIdx.y;
    const int h = bh & 15;
    const int t = threadIdx.x;
    const float dec = 1.f / (1.f + expf(-decay_logits[h]));
    __shared__ float sw[CLEN][6], sr[CLEN][6], sa[CLEN][6];
    __shared__ float sred[42];
    size_t base = ((size_t)bh * CT + c * CLEN + t) * 6;
#pragma unroll
    for (int k = 0; k < 6; k++) {
        sw[t][k] = g_Jw[base + k];
        sr[t][k] = g_Jr[base + k];
        sa[t][k] = g_rd[base + k];
    }
    if (t < 42) sred[t] = 0.f;
    __syncthreads();
    float aw[6], ar[6], cw[6], cr[6];
#pragma unroll
    for (int k = 0; k < 6; k++) { aw[k] = sa[t][k]; ar[k] = sw[t][k]; cw[k] = sw[t][k]; cr[k] = sr[t][k]; }

    float accw = 0.f, accr = 0.f, wgt = dec;
    for (int s = t - 1; s >= 0; s--) {
        float dw = 0.f, dr = 0.f;
#pragma unroll
        for (int k = 0; k < 6; k++) { dw += aw[k] * sw[s][k]; dr += ar[k] * sr[s][k]; }
        accw += wgt * dw * dw;
        accr += wgt * dr * dr;
        wgt *= dec;
    }
    g_intraw[bh * CT + c * CLEN + t] = accw;
    g_intrar[bh * CT + c * CLEN + t] = accr;

    float wl = expf(logf(dec) * (float)(CLEN - t));
    float redw[21], redr[21];
    {
        int e = 0;
#pragma unroll
        for (int i = 0; i < 6; i++)
#pragma unroll
            for (int jj = i; jj < 6; jj++) {
                redw[e] = wl * cw[i] * cw[jj];
                redr[e] = wl * cr[i] * cr[jj];
                e++;
            }
    }
#pragma unroll
    for (int e = 0; e < 21; e++) {
        float vw = redw[e], vr = redr[e];
#pragma unroll
        for (int msk = 16; msk; msk >>= 1) {
            vw += __shfl_xor_sync(0xffffffffu, vw, msk);
            vr += __shfl_xor_sync(0xffffffffu, vr, msk);
        }
        if ((t & 31) == 0) {
            atomicAdd(&sred[e], vw);
            atomicAdd(&sred[21 + e], vr);
        }
    }
    __syncthreads();
    if (t < 42) g_L[((size_t)bh * NCH + c) * 42 + t] = sred[t];
}

// ---------------- scan B: sequential chunk combine ----------------
__global__ void rw_scanB(const float* __restrict__ decay_logits) {
    int bh = blockIdx.x, e = threadIdx.x;
    if (e >= 42) return;
    float dec = 1.f / (1.f + expf(-decay_logits[bh & 15]));
    float dC = expf(logf(dec) * (float)CLEN);
    float M = 0.f;
    for (int c = 0; c < NCH; c++) {
        g_Ms[((size_t)bh * NCH + c) * 42 + e] = M;
        M = dC * M + g_L[((size_t)bh * NCH + c) * 42 + e];
    }
}

// ---------------- scan C: per-t quadratic forms + mix ----------------
__global__ __launch_bounds__(128) void rw_scanC(const float* __restrict__ decay_logits,
                                                const float* __restrict__ rw_mix) {
    int bh = blockIdx.x, c = blockIdx.y, t = threadIdx.x;
    int h = bh & 15;
    float dec = 1.f / (1.f + expf(-decay_logits[h]));
    float alpha = 1.f / (1.f + expf(-rw_mix[0]));
    __shared__ float sM[42];
    if (t < 42) sM[t] = g_Ms[((size_t)bh * NCH + c) * 42 + t];
    __syncthreads();
    int tt = c * CLEN + t;
    size_t base = ((size_t)bh * CT + tt) * 6;
    float aw[6], ar[6];
#pragma unroll
    for (int k = 0; k < 6; k++) { aw[k] = g_rd[base + k]; ar[k] = g_Jw[base + k]; }
    float qw = 0.f, qr = 0.f;
    {
        int e = 0;
#pragma unroll
        for (int i = 0; i < 6; i++)
#pragma unroll
            for (int jj = i; jj < 6; jj++) {
                float f = (i == jj) ? 1.f : 2.f;
                qw += f * sM[e] * aw[i] * aw[jj];
                qr += f * sM[21 + e] * ar[i] * ar[jj];
                e++;
            }
    }
    float dp = expf(logf(dec) * (float)t);
    float scw = g_intraw[bh * CT + tt] + dp * qw;
    float scr = g_intrar[bh * CT + tt] + dp * qr;
    g_score[bh * CT + tt] = (1.f - alpha) * scw + alpha * scr;
}

// ---------------- gating: mean over heads ----------------
__global__ void rw_gate(const float* __restrict__ mem_scale, const float* __restrict__ memg_b) {
    int bt = blockIdx.x * 256 + threadIdx.x;
    if (bt >= CBT) return;
    int b = bt >> 11, t = bt & (CT - 1);
    float s = 0.f;
#pragma unroll
    for (int h = 0; h < CH; h++) {
        float ms = g_score[(b * CH + h) * CT + t];
        float gp = g_P[(size_t)bt * 272 + 256 + h] + memg_b[h];
        s += sigf(ms * mem_scale[h]) * sigf(gp);
    }
    g_gated[bt] = s * (1.f / 16.f);
}

// ---------------- launch ----------------
extern "C" void kernel_launch(void* const* d_in, const int* in_sizes, int n_in,
                              void* d_out, int out_size) {
    (void)in_sizes; (void)n_in; (void)out_size;
    const float* x            = (const float*)d_in[0];
    const float* qkv_w        = (const float*)d_in[1];
    const float* qkv_b        = (const float*)d_in[2];
    const float* w1w          = (const float*)d_in[3];
    const float* w2w          = (const float*)d_in[4];
    const float* w1r          = (const float*)d_in[5];
    const float* w2r          = (const float*)d_in[6];
    const float* memv_w       = (const float*)d_in[7];
    const float* memv_b       = (const float*)d_in[8];
    const float* memg_w       = (const float*)d_in[9];
    const float* memg_b       = (const float*)d_in[10];
    const float* mem_scale    = (const float*)d_in[11];
    const float* rw_mix       = (const float*)d_in[12];
    const float* out_w        = (const float*)d_in[13];
    const float* out_b        = (const float*)d_in[14];
    const float* decay_logits = (const float*)d_in[15];

    float *p_qkv, *p_seq, *p_z, *p_P, *p_sw, *p_gated;
    cudaGetSymbolAddress((void**)&p_qkv,   g_qkv);
    cudaGetSymbolAddress((void**)&p_seq,   g_seqout);
    cudaGetSymbolAddress((void**)&p_z,     g_z);
    cudaGetSymbolAddress((void**)&p_P,     g_P);
    cudaGetSymbolAddress((void**)&p_sw,    g_smallW);
    cudaGetSymbolAddress((void**)&p_gated, g_gated);

    rw_concat_w<<<(CD * 272 + 255) / 256, 256>>>(w1w, w2w, w1r, w2r, memg_w);
    rw_gemm<<<dim3(QKVLD / 64, CBT / 128), 256>>>(x, CD, qkv_w, QKVLD, qkv_b,
                                                  p_qkv, QKVLD, QKVLD, 0, nullptr, nullptr);
    rw_gemm<<<dim3(5, CBT / 128), 256>>>(x, CD, p_sw, 272, nullptr,
                                         p_P, 272, 272, 0, nullptr, nullptr);
    rw_attn<<<dim3(CT / 64, NBH), 256>>>();
    rw_lines<<<(CBT * CH + 255) / 256, 256>>>();
    rw_scanA<<<dim3(NBH, NCH), 128>>>(decay_logits);
    rw_scanB<<<NBH, 64>>>(decay_logits);
    rw_scanC<<<dim3(NBH, NCH), 128>>>(decay_logits, rw_mix);
    rw_gate<<<(CBT + 255) / 256, 256>>>(mem_scale, memg_b);
    rw_gemm<<<dim3(CD / 64, CBT / 128), 256>>>(x, CD, memv_w, CD, memv_b,
                                               p_z, CD, CD, 1, p_seq, p_gated);
    rw_gemm<<<dim3(CD / 64, CBT / 128), 256>>>(p_z, CD, out_w, CD, out_b,
                                               (float*)d_out, CD, CD, 0, nullptr, nullptr);
}

// round 8
// speedup vs baseline: 1.0098x; 1.0098x over previous
#include <cuda_runtime.h>
#include <math.h>

#define CB 2
#define CT 2048
#define CD 1024
#define CH 16
#define CBT 4096            // B*T
#define QKVLD 3072
#define NBH 32              // B*H
#define NCH 16              // chunks over T
#define CLEN 128            // chunk length

// ---------------- scratch (device globals; no runtime allocation) ----------------
__device__ float g_qkv[(size_t)CBT * QKVLD];
__device__ float g_seqout[(size_t)CBT * CD];
__device__ float g_z[(size_t)CBT * CD];
__device__ float g_P[(size_t)CBT * 272];      // [w1|w2|r1|r2|gate_pre]
__device__ float g_smallW[(size_t)CD * 272];
__device__ float g_Jw[NBH * CT * 6];
__device__ float g_Jr[NBH * CT * 6];
__device__ float g_rd[NBH * CT * 6];
__device__ float g_intraw[NBH * CT];
__device__ float g_intrar[NBH * CT];
__device__ float g_L[NBH * NCH * 42];
__device__ float g_Ms[NBH * NCH * 42];
__device__ float g_score[NBH * CT];
__device__ float g_gated[CBT];

__device__ __forceinline__ float sigf(float x) { return 1.f / (1.f + __expf(-x)); }

// ---------------- concat small weights into [1024 x 272] ----------------
__global__ void rw_concat_w(const float* __restrict__ w1w, const float* __restrict__ w2w,
                            const float* __restrict__ w1r, const float* __restrict__ w2r,
                            const float* __restrict__ memg) {
    int i = blockIdx.x * 256 + threadIdx.x;
    if (i >= CD * 272) return;
    int k = i / 272, n = i % 272;
    float v;
    if (n < 64)       v = w1w[k * 64 + n];
    else if (n < 128) v = w2w[k * 64 + (n - 64)];
    else if (n < 192) v = w1r[k * 64 + (n - 128)];
    else if (n < 256) v = w2r[k * 64 + (n - 192)];
    else              v = memg[k * 16 + (n - 256)];
    g_smallW[i] = v;
}

// ---------------- fp32 GEMM: C[M,N] = A[M,1024] @ W[1024,N] (+bias) ----------------
// mode=1: C = seqout + gated[m] * (acc + bias)
__global__ __launch_bounds__(256) void rw_gemm(
    const float* __restrict__ A, int lda,
    const float* __restrict__ W, int ldw,
    const float* __restrict__ bias,
    float* __restrict__ C, int ldc, int N,
    int mode, const float* __restrict__ seqout, const float* __restrict__ gated) {
    __shared__ float As[16][132];
    __shared__ float Bs[16][68];
    const int tid = threadIdx.x;
    const int tx = tid & 15, ty = tid >> 4;
    const int m0 = blockIdx.y * 128;
    const int n0 = blockIdx.x * 64;

    float acc[8][4];
#pragma unroll
    for (int i = 0; i < 8; i++)
#pragma unroll
        for (int j = 0; j < 4; j++) acc[i][j] = 0.f;

    for (int k0 = 0; k0 < CD; k0 += 16) {
#pragma unroll
        for (int u = 0; u < 2; u++) {
            int idx = tid + u * 256;
            int row = idx >> 2;
            int kk = (idx & 3) << 2;
            float4 v = *(const float4*)(A + (size_t)(m0 + row) * lda + k0 + kk);
            As[kk + 0][row] = v.x; As[kk + 1][row] = v.y;
            As[kk + 2][row] = v.z; As[kk + 3][row] = v.w;
        }
        {
            int kk = tid >> 4;
            int j = (tid & 15) << 2;
            float4 v = make_float4(0.f, 0.f, 0.f, 0.f);
            if (n0 + j < N) v = *(const float4*)(W + (size_t)(k0 + kk) * ldw + n0 + j);
            *(float4*)&Bs[kk][j] = v;
        }
        __syncthreads();
#pragma unroll
        for (int kk = 0; kk < 16; kk++) {
            float4 a0 = *(const float4*)&As[kk][ty * 8];
            float4 a1 = *(const float4*)&As[kk][ty * 8 + 4];
            float4 b  = *(const float4*)&Bs[kk][tx * 4];
            float av[8] = {a0.x, a0.y, a0.z, a0.w, a1.x, a1.y, a1.z, a1.w};
            float bv[4] = {b.x, b.y, b.z, b.w};
#pragma unroll
            for (int i = 0; i < 8; i++)
#pragma unroll
                for (int j = 0; j < 4; j++) acc[i][j] += av[i] * bv[j];
        }
        __syncthreads();
    }
#pragma unroll
    for (int i = 0; i < 8; i++) {
        int m = m0 + ty * 8 + i;
#pragma unroll
        for (int j = 0; j < 4; j++) {
            int n = n0 + tx * 4 + j;
            if (n < N) {
                float v = acc[i][j];
                if (bias) v += bias[n];
                if (mode) v = seqout[(size_t)m * CD + n] + gated[m] * v;
                C[(size_t)m * ldc + n] = v;
            }
        }
    }
}

// ---------------- flash attention, 64q x 64k tiles, DH=64 ----------------
#define SWK(d, c) ((c) ^ ((((d) >> 2) & 7) << 2))
#define SWP(q, c) ((c) ^ (((q) & 7) << 2))

__global__ __launch_bounds__(256) void rw_attn() {
    __shared__ float Qs[64][64];   // [d][q] swizzled, pre-scaled
    __shared__ float KP[64][64];   // K as [d][k] swizzled; reused as P [q][k] swizzled
    __shared__ float Vs[64][64];   // [k][d]
    const int tid = threadIdx.x;
    const int tx = tid & 15, ty = tid >> 4;
    const int qi = blockIdx.x;
    const int b = blockIdx.y >> 4, h = blockIdx.y & 15;

#pragma unroll
    for (int u = 0; u < 4; u++) {
        int idx = tid + u * 256;
        int r = idx >> 4;
        int dd = (idx & 15) << 2;
        const float* p = g_qkv + (size_t)(b * CT + qi * 64 + r) * QKVLD + h * 64 + dd;
        float4 v = *(const float4*)p;
        Qs[dd + 0][SWK(dd + 0, r)] = v.x * 0.125f;
        Qs[dd + 1][SWK(dd + 1, r)] = v.y * 0.125f;
        Qs[dd + 2][SWK(dd + 2, r)] = v.z * 0.125f;
        Qs[dd + 3][SWK(dd + 3, r)] = v.w * 0.125f;
    }

    float O[4][4], mi[4], li[4];
#pragma unroll
    for (int i = 0; i < 4; i++) {
        mi[i] = -1e30f; li[i] = 0.f;
#pragma unroll
        for (int j = 0; j < 4; j++) O[i][j] = 0.f;
    }

    for (int j = 0; j <= qi; j++) {
        __syncthreads();
#pragma unroll
        for (int u = 0; u < 4; u++) {
            int idx = tid + u * 256;
            int r = idx >> 4;
            int dd = (idx & 15) << 2;
            const float* kp = g_qkv + (size_t)(b * CT + j * 64 + r) * QKVLD + CD + h * 64 + dd;
            float4 kv = *(const float4*)kp;
            KP[dd + 0][SWK(dd + 0, r)] = kv.x;
            KP[dd + 1][SWK(dd + 1, r)] = kv.y;
            KP[dd + 2][SWK(dd + 2, r)] = kv.z;
            KP[dd + 3][SWK(dd + 3, r)] = kv.w;
            float4 vv = *(const float4*)(kp + CD);
            *(float4*)&Vs[r][dd] = vv;
        }
        __syncthreads();

        float s[4][4];
#pragma unroll
        for (int i = 0; i < 4; i++)
#pragma unroll
            for (int jj = 0; jj < 4; jj++) s[i][jj] = 0.f;
#pragma unroll 8
        for (int d = 0; d < 64; d++) {
            float4 a  = *(const float4*)&Qs[d][SWK(d, ty * 4)];
            float4 bb = *(const float4*)&KP[d][SWK(d, tx * 4)];
            float av[4] = {a.x, a.y, a.z, a.w};
            float bv[4] = {bb.x, bb.y, bb.z, bb.w};
#pragma unroll
            for (int i = 0; i < 4; i++)
#pragma unroll
                for (int jj = 0; jj < 4; jj++) s[i][jj] += av[i] * bv[jj];
        }
        __syncthreads();   // done reading K, KP can become P

        if (j == qi) {
#pragma unroll
            for (int i = 0; i < 4; i++)
#pragma unroll
                for (int jj = 0; jj < 4; jj++)
                    if (tx * 4 + jj > ty * 4 + i) s[i][jj] = -1e30f;
        }

#pragma unroll
        for (int i = 0; i < 4; i++) {
            float mloc = fmaxf(fmaxf(s[i][0], s[i][1]), fmaxf(s[i][2], s[i][3]));
#pragma unroll
            for (int msk = 8; msk; msk >>= 1)
                mloc = fmaxf(mloc, __shfl_xor_sync(0xffffffffu, mloc, msk));
            float mnew = fmaxf(mi[i], mloc);
            float corr = __expf(mi[i] - mnew);
            mi[i] = mnew;
            float p0 = __expf(s[i][0] - mnew);
            float p1 = __expf(s[i][1] - mnew);
            float p2 = __expf(s[i][2] - mnew);
            float p3 = __expf(s[i][3] - mnew);
            float lsum = p0 + p1 + p2 + p3;
#pragma unroll
            for (int msk = 8; msk; msk >>= 1)
                lsum += __shfl_xor_sync(0xffffffffu, lsum, msk);
            li[i] = li[i] * corr + lsum;
#pragma unroll
            for (int jj = 0; jj < 4; jj++) O[i][jj] *= corr;
            int q = ty * 4 + i;
            *(float4*)&KP[q][SWP(q, tx * 4)] = make_float4(p0, p1, p2, p3);
        }
        __syncthreads();

#pragma unroll 8
        for (int k = 0; k < 64; k++) {
            float4 vv = *(const float4*)&Vs[k][tx * 4];
            float vb[4] = {vv.x, vv.y, vv.z, vv.w};
            float pw[4];
#pragma unroll
            for (int i = 0; i < 4; i++) pw[i] = KP[ty * 4 + i][SWP(ty * 4 + i, k)];
#pragma unroll
            for (int i = 0; i < 4; i++)
#pragma unroll
                for (int jj = 0; jj < 4; jj++) O[i][jj] += pw[i] * vb[jj];
        }
    }

#pragma unroll
    for (int i = 0; i < 4; i++) {
        float inv = 1.f / li[i];
        float4 o = make_float4(O[i][0] * inv, O[i][1] * inv, O[i][2] * inv, O[i][3] * inv);
        *(float4*)(g_seqout + (size_t)(b * CT + qi * 64 + ty * 4 + i) * CD + h * 64 + tx * 4) = o;
    }
}

// ---------------- Plucker lines ----------------
__global__ __launch_bounds__(256) void rw_lines() {
    int idx = blockIdx.x * 256 + threadIdx.x;
    if (idx >= CBT * CH) return;
    int h = idx & 15, bt = idx >> 4;
    int b = bt >> 11, t = bt & (CT - 1);
    const float* Pr = g_P + (size_t)bt * 272;
    float w1[4] = {0.f, 0.f, 0.f, 0.f}, w2[4], r1[4], r2[4];
    if (t > 0) {
        const float* Pp = g_P + (size_t)(bt - 1) * 272;
#pragma unroll
        for (int k = 0; k < 4; k++) w1[k] = Pp[h * 4 + k];
    }
#pragma unroll
    for (int k = 0; k < 4; k++) {
        w2[k] = Pr[64 + h * 4 + k];
        r1[k] = Pr[128 + h * 4 + k];
        r2[k] = Pr[192 + h * 4 + k];
    }
    float Lw[6], Lr[6];
    Lw[0] = w1[0]*w2[1] - w1[1]*w2[0];
    Lw[1] = w1[0]*w2[2] - w1[2]*w2[0];
    Lw[2] = w1[0]*w2[3] - w1[3]*w2[0];
    Lw[3] = w1[1]*w2[2] - w1[2]*w2[1];
    Lw[4] = w1[1]*w2[3] - w1[3]*w2[1];
    Lw[5] = w1[2]*w2[3] - w1[3]*w2[2];
    Lr[0] = r1[0]*r2[1] - r1[1]*r2[0];
    Lr[1] = r1[0]*r2[2] - r1[2]*r2[0];
    Lr[2] = r1[0]*r2[3] - r1[3]*r2[0];
    Lr[3] = r1[1]*r2[2] - r1[2]*r2[1];
    Lr[4] = r1[1]*r2[3] - r1[3]*r2[1];
    Lr[5] = r1[2]*r2[3] - r1[3]*r2[2];
    float nw = 0.f, nr = 0.f;
#pragma unroll
    for (int k = 0; k < 6; k++) { nw += Lw[k]*Lw[k]; nr += Lr[k]*Lr[k]; }
    float iw = 1.f / fmaxf(sqrtf(nw), 1e-12f);
    float ir = 1.f / fmaxf(sqrtf(nr), 1e-12f);
#pragma unroll
    for (int k = 0; k < 6; k++) { Lw[k] *= iw; Lr[k] *= ir; }
    int bh = b * CH + h;
    size_t base = ((size_t)bh * CT + t) * 6;
    // Jv = (v5, -v4, v3, v2, -v1, v0)
    g_Jw[base+0] =  Lw[5]; g_Jw[base+1] = -Lw[4]; g_Jw[base+2] = Lw[3];
    g_Jw[base+3] =  Lw[2]; g_Jw[base+4] = -Lw[1]; g_Jw[base+5] = Lw[0];
    g_Jr[base+0] =  Lr[5]; g_Jr[base+1] = -Lr[4]; g_Jr[base+2] = Lr[3];
    g_Jr[base+3] =  Lr[2]; g_Jr[base+4] = -Lr[1]; g_Jr[base+5] = Lr[0];
#pragma unroll
    for (int k = 0; k < 6; k++) g_rd[base + k] = Lr[k];
}

// ---------------- scan A: intra-chunk scores + local 6x6 sym matrices ----------------
__global__ __launch_bounds__(128) void rw_scanA(const float* __restrict__ decay_logits) {
    const int bh = blockIdx.x, c = blockIdx.y;
    const int h = bh & 15;
    const int t = threadIdx.x;
    const float dec = 1.f / (1.f + expf(-decay_logits[h]));
    __shared__ float sw[CLEN][6], sr[CLEN][6], sa[CLEN][6];
    __shared__ float sred[42];
    size_t base = ((size_t)bh * CT + c * CLEN + t) * 6;
#pragma unroll
    for (int k = 0; k < 6; k++) {
        sw[t][k] = g_Jw[base + k];
        sr[t][k] = g_Jr[base + k];
        sa[t][k] = g_rd[base + k];
    }
    if (t < 42) sred[t] = 0.f;
    __syncthreads();
    float aw[6], ar[6], cw[6], cr[6];
#pragma unroll
    for (int k = 0; k < 6; k++) { aw[k] = sa[t][k]; ar[k] = sw[t][k]; cw[k] = sw[t][k]; cr[k] = sr[t][k]; }

    float accw = 0.f, accr = 0.f, wgt = dec;
    for (int s = t - 1; s >= 0; s--) {
        float dw = 0.f, dr = 0.f;
#pragma unroll
        for (int k = 0; k < 6; k++) { dw += aw[k] * sw[s][k]; dr += ar[k] * sr[s][k]; }
        accw += wgt * dw * dw;
        accr += wgt * dr * dr;
        wgt *= dec;
    }
    g_intraw[bh * CT + c * CLEN + t] = accw;
    g_intrar[bh * CT + c * CLEN + t] = accr;

    float wl = expf(logf(dec) * (float)(CLEN - t));
    float redw[21], redr[21];
    {
        int e = 0;
#pragma unroll
        for (int i = 0; i < 6; i++)
#pragma unroll
            for (int jj = i; jj < 6; jj++) {
                redw[e] = wl * cw[i] * cw[jj];
                redr[e] = wl * cr[i] * cr[jj];
                e++;
            }
    }
#pragma unroll
    for (int e = 0; e < 21; e++) {
        float vw = redw[e], vr = redr[e];
#pragma unroll
        for (int msk = 16; msk; msk >>= 1) {
            vw += __shfl_xor_sync(0xffffffffu, vw, msk);
            vr += __shfl_xor_sync(0xffffffffu, vr, msk);
        }
        if ((t & 31) == 0) {
            atomicAdd(&sred[e], vw);
            atomicAdd(&sred[21 + e], vr);
        }
    }
    __syncthreads();
    if (t < 42) g_L[((size_t)bh * NCH + c) * 42 + t] = sred[t];
}

// ---------------- scan B: sequential chunk combine ----------------
__global__ void rw_scanB(const float* __restrict__ decay_logits) {
    int bh = blockIdx.x, e = threadIdx.x;
    if (e >= 42) return;
    float dec = 1.f / (1.f + expf(-decay_logits[bh & 15]));
    float dC = expf(logf(dec) * (float)CLEN);
    float M = 0.f;
    for (int c = 0; c < NCH; c++) {
        g_Ms[((size_t)bh * NCH + c) * 42 + e] = M;
        M = dC * M + g_L[((size_t)bh * NCH + c) * 42 + e];
    }
}

// ---------------- scan C: per-t quadratic forms + mix ----------------
__global__ __launch_bounds__(128) void rw_scanC(const float* __restrict__ decay_logits,
                                                const float* __restrict__ rw_mix) {
    int bh = blockIdx.x, c = blockIdx.y, t = threadIdx.x;
    int h = bh & 15;
    float dec = 1.f / (1.f + expf(-decay_logits[h]));
    float alpha = 1.f / (1.f + expf(-rw_mix[0]));
    __shared__ float sM[42];
    if (t < 42) sM[t] = g_Ms[((size_t)bh * NCH + c) * 42 + t];
    __syncthreads();
    int tt = c * CLEN + t;
    size_t base = ((size_t)bh * CT + tt) * 6;
    float aw[6], ar[6];
#pragma unroll
    for (int k = 0; k < 6; k++) { aw[k] = g_rd[base + k]; ar[k] = g_Jw[base + k]; }
    float qw = 0.f, qr = 0.f;
    {
        int e = 0;
#pragma unroll
        for (int i = 0; i < 6; i++)
#pragma unroll
            for (int jj = i; jj < 6; jj++) {
                float f = (i == jj) ? 1.f : 2.f;
                qw += f * sM[e] * aw[i] * aw[jj];
                qr += f * sM[21 + e] * ar[i] * ar[jj];
                e++;
            }
    }
    float dp = expf(logf(dec) * (float)t);
    float scw = g_intraw[bh * CT + tt] + dp * qw;
    float scr = g_intrar[bh * CT + tt] + dp * qr;
    g_score[bh * CT + tt] = (1.f - alpha) * scw + alpha * scr;
}

// ---------------- gating: mean over heads ----------------
__global__ void rw_gate(const float* __restrict__ mem_scale, const float* __restrict__ memg_b) {
    int bt = blockIdx.x * 256 + threadIdx.x;
    if (bt >= CBT) return;
    int b = bt >> 11, t = bt & (CT - 1);
    float s = 0.f;
#pragma unroll
    for (int h = 0; h < CH; h++) {
        float ms = g_score[(b * CH + h) * CT + t];
        float gp = g_P[(size_t)bt * 272 + 256 + h] + memg_b[h];
        s += sigf(ms * mem_scale[h]) * sigf(gp);
    }
    g_gated[bt] = s * (1.f / 16.f);
}

// ---------------- launch ----------------
extern "C" void kernel_launch(void* const* d_in, const int* in_sizes, int n_in,
                              void* d_out, int out_size) {
    (void)in_sizes; (void)n_in; (void)out_size;
    const float* x            = (const float*)d_in[0];
    const float* qkv_w        = (const float*)d_in[1];
    const float* qkv_b        = (const float*)d_in[2];
    const float* w1w          = (const float*)d_in[3];
    const float* w2w          = (const float*)d_in[4];
    const float* w1r          = (const float*)d_in[5];
    const float* w2r          = (const float*)d_in[6];
    const float* memv_w       = (const float*)d_in[7];
    const float* memv_b       = (const float*)d_in[8];
    const float* memg_w       = (const float*)d_in[9];
    const float* memg_b       = (const float*)d_in[10];
    const float* mem_scale    = (const float*)d_in[11];
    const float* rw_mix       = (const float*)d_in[12];
    const float* out_w        = (const float*)d_in[13];
    const float* out_b        = (const float*)d_in[14];
    const float* decay_logits = (const float*)d_in[15];

    float *p_qkv, *p_seq, *p_z, *p_P, *p_sw, *p_gated;
    cudaGetSymbolAddress((void**)&p_qkv,   g_qkv);
    cudaGetSymbolAddress((void**)&p_seq,   g_seqout);
    cudaGetSymbolAddress((void**)&p_z,     g_z);
    cudaGetSymbolAddress((void**)&p_P,     g_P);
    cudaGetSymbolAddress((void**)&p_sw,    g_smallW);
    cudaGetSymbolAddress((void**)&p_gated, g_gated);

    rw_concat_w<<<(CD * 272 + 255) / 256, 256>>>(w1w, w2w, w1r, w2r, memg_w);
    rw_gemm<<<dim3(QKVLD / 64, CBT / 128), 256>>>(x, CD, qkv_w, QKVLD, qkv_b,
                                                  p_qkv, QKVLD, QKVLD, 0, nullptr, nullptr);
    rw_gemm<<<dim3(5, CBT / 128), 256>>>(x, CD, p_sw, 272, nullptr,
                                         p_P, 272, 272, 0, nullptr, nullptr);
    rw_attn<<<dim3(CT / 64, NBH), 256>>>();
    rw_lines<<<(CBT * CH + 255) / 256, 256>>>();
    rw_scanA<<<dim3(NBH, NCH), 128>>>(decay_logits);
    rw_scanB<<<NBH, 64>>>(decay_logits);
    rw_scanC<<<dim3(NBH, NCH), 128>>>(decay_logits, rw_mix);
    rw_gate<<<(CBT + 255) / 256, 256>>>(mem_scale, memg_b);
    rw_gemm<<<dim3(CD / 64, CBT / 128), 256>>>(x, CD, memv_w, CD, memv_b,
                                               p_z, CD, CD, 1, p_seq, p_gated);
    rw_gemm<<<dim3(CD / 64, CBT / 128), 256>>>(p_z, CD, out_w, CD, out_b,
                                               (float*)d_out, CD, CD, 0, nullptr, nullptr);
}

// round 14
// speedup vs baseline: 1.5187x; 1.5039x over previous
#include <cuda_runtime.h>
#include <cuda_bf16.h>
#include <math.h>
#include <stdint.h>

#define CB 2
#define CT 2048
#define CD 1024
#define CH 16
#define CBT 4096
#define QKVLD 3072
#define NBH 32
#define NCH 16
#define CLEN 128

__device__ float g_qkv[(size_t)CBT * QKVLD];
__device__ float g_seqout[(size_t)CBT * CD];
__device__ float g_z[(size_t)CBT * CD];
__device__ float g_P[(size_t)CBT * 272];
__device__ float g_smallW[(size_t)CD * 272];
__device__ float g_Jw[NBH * CT * 6];
__device__ float g_Jr[NBH * CT * 6];
__device__ float g_rd[NBH * CT * 6];
__device__ float g_intraw[NBH * CT];
__device__ float g_intrar[NBH * CT];
__device__ float g_L[NBH * NCH * 42];
__device__ float g_Ms[NBH * NCH * 42];
__device__ float g_score[NBH * CT];
__device__ float g_gated[CBT];

__device__ __align__(16) __nv_bfloat16 g_xh[(size_t)CBT * CD];
__device__ __align__(16) __nv_bfloat16 g_xl[(size_t)CBT * CD];
__device__ __align__(16) __nv_bfloat16 g_zh[(size_t)CBT * CD];
__device__ __align__(16) __nv_bfloat16 g_zl[(size_t)CBT * CD];
__device__ __align__(16) __nv_bfloat16 g_wqh[(size_t)QKVLD * CD];
__device__ __align__(16) __nv_bfloat16 g_wql[(size_t)QKVLD * CD];
__device__ __align__(16) __nv_bfloat16 g_wvh[(size_t)CD * CD];
__device__ __align__(16) __nv_bfloat16 g_wvl[(size_t)CD * CD];
__device__ __align__(16) __nv_bfloat16 g_woh[(size_t)CD * CD];
__device__ __align__(16) __nv_bfloat16 g_wol[(size_t)CD * CD];

__device__ __forceinline__ float sigf(float x) { return 1.f / (1.f + __expf(-x)); }

__device__ __forceinline__ uint32_t s2u(const void* p) {
    uint32_t a;
    asm("{ .reg .u64 t; cvta.to.shared.u64 t, %1; cvt.u32.u64 %0, t; }" : "=r"(a) : "l"(p));
    return a;
}

// ===================== baseline-PTX tensor-core primitives (sm_80+ feature set) =====================
#define LDMX4(r, a) asm volatile( \
    "ldmatrix.sync.aligned.m8n8.x4.shared.b16 {%0,%1,%2,%3}, [%4];" \
    : "=r"((r)[0]), "=r"((r)[1]), "=r"((r)[2]), "=r"((r)[3]) : "r"(a))

#define MMA16816(c, a, b0, b1) asm volatile( \
    "mma.sync.aligned.m16n8k16.row.col.f32.bf16.bf16.f32 " \
    "{%0,%1,%2,%3}, {%4,%5,%6,%7}, {%8,%9}, {%0,%1,%2,%3};" \
    : "+f"((c)[0]), "+f"((c)[1]), "+f"((c)[2]), "+f"((c)[3]) \
    : "r"((a)[0]), "r"((a)[1]), "r"((a)[2]), "r"((a)[3]), "r"(b0), "r"(b1))

#define CPA(dst, src) asm volatile("cp.async.cg.shared.global [%0], [%1], 16;" :: "r"(dst), "l"(src))
#define CPC() asm volatile("cp.async.commit_group;" ::: "memory")
#define CPW(n) asm volatile("cp.async.wait_group %0;" :: "n"(n) : "memory")
#define SWZ(b) ((b) ^ (((b) >> 3) & 0x30))

// ---------------- split / transpose-split ----------------
__global__ void rw_split(const float* __restrict__ in, __nv_bfloat16* __restrict__ hi,
                         __nv_bfloat16* __restrict__ lo, int n) {
    int i = blockIdx.x * 256 + threadIdx.x;
    if (i >= n) return;
    float v = in[i];
    __nv_bfloat16 h = __float2bfloat16(v);
    hi[i] = h;
    lo[i] = __float2bfloat16(v - __bfloat162float(h));
}

__global__ void rw_splitT(const float* __restrict__ W, __nv_bfloat16* __restrict__ Th,
                          __nv_bfloat16* __restrict__ Tl, int N) {
    __shared__ float t[32][33];
    int n0 = blockIdx.x * 32, k0 = blockIdx.y * 32;
    for (int i = threadIdx.y; i < 32; i += 8)
        t[i][threadIdx.x] = W[(size_t)(k0 + i) * N + n0 + threadIdx.x];
    __syncthreads();
    for (int i = threadIdx.y; i < 32; i += 8) {
        float v = t[threadIdx.x][i];
        __nv_bfloat16 h = __float2bfloat16(v);
        size_t o = (size_t)(n0 + i) * CD + k0 + threadIdx.x;
        Th[o] = h;
        Tl[o] = __float2bfloat16(v - __bfloat162float(h));
    }
}

// ---------------- split-bf16 tensor-core GEMM ----------------
// C[4096][N] = A[4096][1024] @ Bt[N][1024]^T,  C += via 3 terms: Ah*Bh + Al*Bh + Ah*Bl
// CTA tile 128x128, 8 warps (2m x 4n), warp tile 64x32. K-chunk 32, 2-stage cp.async.
// smem per stage: Ah(8K) Al(8K) Bh(8K) Bl(8K) = 32KB; 2 stages = 64KB dynamic.
__global__ __launch_bounds__(256) void rw_gemm_mma(
    const __nv_bfloat16* __restrict__ Ah, const __nv_bfloat16* __restrict__ Al,
    const __nv_bfloat16* __restrict__ Bh, const __nv_bfloat16* __restrict__ Bl,
    const float* __restrict__ bias, float* __restrict__ C, int N, int mode,
    const float* __restrict__ seqout, const float* __restrict__ gated) {
    extern __shared__ __align__(16) char smem[];
    const int tid = threadIdx.x;
    const int lane = tid & 31, wid = tid >> 5;
    const int wm = wid >> 2, wn = wid & 3;
    const int m0 = blockIdx.y * 128, n0 = blockIdx.x * 128;
    const uint32_t sb0 = s2u(smem);

    float acc[4][4][4];
#pragma unroll
    for (int i = 0; i < 4; i++)
#pragma unroll
        for (int j = 0; j < 4; j++)
#pragma unroll
            for (int k = 0; k < 4; k++) acc[i][j][k] = 0.f;

    const __nv_bfloat16* gAh = Ah + (size_t)m0 * CD;
    const __nv_bfloat16* gAl = Al + (size_t)m0 * CD;
    const __nv_bfloat16* gBh = Bh + (size_t)n0 * CD;
    const __nv_bfloat16* gBl = Bl + (size_t)n0 * CD;

    const int r_ld = tid >> 2, g_ld = tid & 3;
    const uint32_t sw0 = SWZ((uint32_t)(r_ld * 64 + g_ld * 16));
    const uint32_t sw1 = SWZ((uint32_t)((r_ld + 64) * 64 + g_ld * 16));
    const size_t go0 = (size_t)r_ld * CD + g_ld * 8;
    const size_t go1 = (size_t)(r_ld + 64) * CD + g_ld * 8;

#define LOADCH(ch, p) do { \
    int _kc = (ch) * 32; \
    uint32_t _sb = sb0 + (p) * 32768; \
    CPA(_sb + sw0,         (const char*)(gAh + go0 + _kc)); \
    CPA(_sb + sw1,         (const char*)(gAh + go1 + _kc)); \
    CPA(_sb + 8192 + sw0,  (const char*)(gAl + go0 + _kc)); \
    CPA(_sb + 8192 + sw1,  (const char*)(gAl + go1 + _kc)); \
    CPA(_sb + 16384 + sw0, (const char*)(gBh + go0 + _kc)); \
    CPA(_sb + 16384 + sw1, (const char*)(gBh + go1 + _kc)); \
    CPA(_sb + 24576 + sw0, (const char*)(gBl + go0 + _kc)); \
    CPA(_sb + 24576 + sw1, (const char*)(gBl + go1 + _kc)); \
    CPC(); \
} while (0)

    LOADCH(0, 0);
    for (int ch = 0; ch < 32; ch++) {
        const int p = ch & 1;
        if (ch + 1 < 32) { LOADCH(ch + 1, p ^ 1); CPW(1); }
        else             { CPW(0); }
        __syncthreads();
        const uint32_t sb = sb0 + p * 32768;
#pragma unroll
        for (int kk = 0; kk < 32; kk += 16) {
            uint32_t bh[2][4], bl[2][4], af[4][4];
#pragma unroll
            for (int j = 0; j < 2; j++) {
                int n = wn * 32 + j * 16 + (lane & 7) + ((lane >> 4) << 3);
                int g = (kk >> 3) + ((lane >> 3) & 1);
                uint32_t ad = sb + 16384 + SWZ((uint32_t)(n * 64 + g * 16));
                LDMX4(bh[j], ad);
                LDMX4(bl[j], ad + 8192);
            }
#pragma unroll
            for (int i = 0; i < 4; i++) {
                int r = wm * 64 + i * 16 + (lane & 15);
                int g = (kk >> 3) + (lane >> 4);
                uint32_t ad = sb + SWZ((uint32_t)(r * 64 + g * 16));
                LDMX4(af[i], ad);
            }
#pragma unroll
            for (int i = 0; i < 4; i++)
#pragma unroll
                for (int j = 0; j < 4; j++) {
                    MMA16816(acc[i][j], af[i], bh[j >> 1][(j & 1) * 2], bh[j >> 1][(j & 1) * 2 + 1]);
                    MMA16816(acc[i][j], af[i], bl[j >> 1][(j & 1) * 2], bl[j >> 1][(j & 1) * 2 + 1]);
                }
#pragma unroll
            for (int i = 0; i < 4; i++) {
                int r = wm * 64 + i * 16 + (lane & 15);
                int g = (kk >> 3) + (lane >> 4);
                uint32_t ad = sb + 8192 + SWZ((uint32_t)(r * 64 + g * 16));
                LDMX4(af[i], ad);
            }
#pragma unroll
            for (int i = 0; i < 4; i++)
#pragma unroll
                for (int j = 0; j < 4; j++)
                    MMA16816(acc[i][j], af[i], bh[j >> 1][(j & 1) * 2], bh[j >> 1][(j & 1) * 2 + 1]);
        }
        __syncthreads();
    }
#undef LOADCH

    const int mb = m0 + wm * 64, nb = n0 + wn * 32;
    const int rr = lane >> 2, cc = (lane & 3) * 2;
#pragma unroll
    for (int i = 0; i < 4; i++) {
        int r0 = mb + i * 16 + rr;
        int r1 = r0 + 8;
        float g0 = 0.f, g1 = 0.f;
        if (mode) { g0 = gated[r0]; g1 = gated[r1]; }
#pragma unroll
        for (int j = 0; j < 4; j++) {
            int col = nb + j * 8 + cc;
            float b0 = bias[col], b1 = bias[col + 1];
            float v0 = acc[i][j][0] + b0, v1 = acc[i][j][1] + b1;
            float v2 = acc[i][j][2] + b0, v3 = acc[i][j][3] + b1;
            if (mode) {
                v0 = seqout[(size_t)r0 * CD + col]     + g0 * v0;
                v1 = seqout[(size_t)r0 * CD + col + 1] + g0 * v1;
                v2 = seqout[(size_t)r1 * CD + col]     + g1 * v2;
                v3 = seqout[(size_t)r1 * CD + col + 1] + g1 * v3;
            }
            *(float2*)(C + (size_t)r0 * N + col) = make_float2(v0, v1);
            *(float2*)(C + (size_t)r1 * N + col) = make_float2(v2, v3);
        }
    }
}

// ---------------- small-weight concat ----------------
__global__ void rw_concat_w(const float* __restrict__ w1w, const float* __restrict__ w2w,
                            const float* __restrict__ w1r, const float* __restrict__ w2r,
                            const float* __restrict__ memg) {
    int i = blockIdx.x * 256 + threadIdx.x;
    if (i >= CD * 272) return;
    int k = i / 272, n = i % 272;
    float v;
    if (n < 64)       v = w1w[k * 64 + n];
    else if (n < 128) v = w2w[k * 64 + (n - 64)];
    else if (n < 192) v = w1r[k * 64 + (n - 128)];
    else if (n < 256) v = w2r[k * 64 + (n - 192)];
    else              v = memg[k * 16 + (n - 256)];
    g_smallW[i] = v;
}

// ---------------- fp32 GEMM (small projections only) ----------------
__global__ __launch_bounds__(256) void rw_gemm(
    const float* __restrict__ A, int lda, const float* __restrict__ W, int ldw,
    float* __restrict__ C, int ldc, int N) {
    __shared__ float As[16][132];
    __shared__ float Bs[16][68];
    const int tid = threadIdx.x;
    const int tx = tid & 15, ty = tid >> 4;
    const int m0 = blockIdx.y * 128, n0 = blockIdx.x * 64;
    float acc[8][4];
#pragma unroll
    for (int i = 0; i < 8; i++)
#pragma unroll
        for (int j = 0; j < 4; j++) acc[i][j] = 0.f;
    for (int k0 = 0; k0 < CD; k0 += 16) {
#pragma unroll
        for (int u = 0; u < 2; u++) {
            int idx = tid + u * 256, row = idx >> 2, kk = (idx & 3) << 2;
            float4 v = *(const float4*)(A + (size_t)(m0 + row) * lda + k0 + kk);
            As[kk][row] = v.x; As[kk + 1][row] = v.y; As[kk + 2][row] = v.z; As[kk + 3][row] = v.w;
        }
        {
            int kk = tid >> 4, j = (tid & 15) << 2;
            float4 v = make_float4(0.f, 0.f, 0.f, 0.f);
            if (n0 + j < N) v = *(const float4*)(W + (size_t)(k0 + kk) * ldw + n0 + j);
            *(float4*)&Bs[kk][j] = v;
        }
        __syncthreads();
#pragma unroll
        for (int kk = 0; kk < 16; kk++) {
            float4 a0 = *(const float4*)&As[kk][ty * 8];
            float4 a1 = *(const float4*)&As[kk][ty * 8 + 4];
            float4 b = *(const float4*)&Bs[kk][tx * 4];
            float av[8] = {a0.x, a0.y, a0.z, a0.w, a1.x, a1.y, a1.z, a1.w};
            float bv[4] = {b.x, b.y, b.z, b.w};
#pragma unroll
            for (int i = 0; i < 8; i++)
#pragma unroll
                for (int j = 0; j < 4; j++) acc[i][j] += av[i] * bv[j];
        }
        __syncthreads();
    }
#pragma unroll
    for (int i = 0; i < 8; i++) {
        int m = m0 + ty * 8 + i;
#pragma unroll
        for (int j = 0; j < 4; j++) {
            int n = n0 + tx * 4 + j;
            if (n < N) C[(size_t)m * ldc + n] = acc[i][j];
        }
    }
}

// ---------------- flash attention (unchanged, passing) ----------------
#define SWKk(d, c) ((c) ^ ((((d) >> 2) & 7) << 2))
#define SWPp(q, c) ((c) ^ (((q) & 7) << 2))

__global__ __launch_bounds__(256) void rw_attn() {
    __shared__ float Qs[64][64];
    __shared__ float KP[64][64];
    __shared__ float Vs[64][64];
    const int tid = threadIdx.x;
    const int tx = tid & 15, ty = tid >> 4;
    const int qi = blockIdx.x;
    const int b = blockIdx.y >> 4, h = blockIdx.y & 15;

#pragma unroll
    for (int u = 0; u < 4; u++) {
        int idx = tid + u * 256, r = idx >> 4, dd = (idx & 15) << 2;
        const float* p = g_qkv + (size_t)(b * CT + qi * 64 + r) * QKVLD + h * 64 + dd;
        float4 v = *(const float4*)p;
        Qs[dd][SWKk(dd, r)] = v.x * 0.125f;
        Qs[dd + 1][SWKk(dd + 1, r)] = v.y * 0.125f;
        Qs[dd + 2][SWKk(dd + 2, r)] = v.z * 0.125f;
        Qs[dd + 3][SWKk(dd + 3, r)] = v.w * 0.125f;
    }
    float O[4][4], mi[4], li[4];
#pragma unroll
    for (int i = 0; i < 4; i++) {
        mi[i] = -1e30f; li[i] = 0.f;
#pragma unroll
        for (int j = 0; j < 4; j++) O[i][j] = 0.f;
    }
    for (int j = 0; j <= qi; j++) {
        __syncthreads();
#pragma unroll
        for (int u = 0; u < 4; u++) {
            int idx = tid + u * 256, r = idx >> 4, dd = (idx & 15) << 2;
            const float* kp = g_qkv + (size_t)(b * CT + j * 64 + r) * QKVLD + CD + h * 64 + dd;
            float4 kv = *(const float4*)kp;
            KP[dd][SWKk(dd, r)] = kv.x;
            KP[dd + 1][SWKk(dd + 1, r)] = kv.y;
            KP[dd + 2][SWKk(dd + 2, r)] = kv.z;
            KP[dd + 3][SWKk(dd + 3, r)] = kv.w;
            float4 vv = *(const float4*)(kp + CD);
            *(float4*)&Vs[r][dd] = vv;
        }
        __syncthreads();
        float s[4][4];
#pragma unroll
        for (int i = 0; i < 4; i++)
#pragma unroll
            for (int jj = 0; jj < 4; jj++) s[i][jj] = 0.f;
#pragma unroll 8
        for (int d = 0; d < 64; d++) {
            float4 a = *(const float4*)&Qs[d][SWKk(d, ty * 4)];
            float4 bb = *(const float4*)&KP[d][SWKk(d, tx * 4)];
            float av[4] = {a.x, a.y, a.z, a.w};
            float bv[4] = {bb.x, bb.y, bb.z, bb.w};
#pragma unroll
            for (int i = 0; i < 4; i++)
#pragma unroll
                for (int jj = 0; jj < 4; jj++) s[i][jj] += av[i] * bv[jj];
        }
        __syncthreads();
        if (j == qi) {
#pragma unroll
            for (int i = 0; i < 4; i++)
#pragma unroll
                for (int jj = 0; jj < 4; jj++)
                    if (tx * 4 + jj > ty * 4 + i) s[i][jj] = -1e30f;
        }
#pragma unroll
        for (int i = 0; i < 4; i++) {
            float mloc = fmaxf(fmaxf(s[i][0], s[i][1]), fmaxf(s[i][2], s[i][3]));
#pragma unroll
            for (int msk = 8; msk; msk >>= 1)
                mloc = fmaxf(mloc, __shfl_xor_sync(0xffffffffu, mloc, msk));
            float mnew = fmaxf(mi[i], mloc);
            float corr = __expf(mi[i] - mnew);
            mi[i] = mnew;
            float p0 = __expf(s[i][0] - mnew), p1 = __expf(s[i][1] - mnew);
            float p2 = __expf(s[i][2] - mnew), p3 = __expf(s[i][3] - mnew);
            float lsum = p0 + p1 + p2 + p3;
#pragma unroll
            for (int msk = 8; msk; msk >>= 1)
                lsum += __shfl_xor_sync(0xffffffffu, lsum, msk);
            li[i] = li[i] * corr + lsum;
#pragma unroll
            for (int jj = 0; jj < 4; jj++) O[i][jj] *= corr;
            int q = ty * 4 + i;
            *(float4*)&KP[q][SWPp(q, tx * 4)] = make_float4(p0, p1, p2, p3);
        }
        __syncthreads();
#pragma unroll 8
        for (int k = 0; k < 64; k++) {
            float4 vv = *(const float4*)&Vs[k][tx * 4];
            float vb[4] = {vv.x, vv.y, vv.z, vv.w};
            float pw[4];
#pragma unroll
            for (int i = 0; i < 4; i++) pw[i] = KP[ty * 4 + i][SWPp(ty * 4 + i, k)];
#pragma unroll
            for (int i = 0; i < 4; i++)
#pragma unroll
                for (int jj = 0; jj < 4; jj++) O[i][jj] += pw[i] * vb[jj];
        }
    }
#pragma unroll
    for (int i = 0; i < 4; i++) {
        float inv = 1.f / li[i];
        float4 o = make_float4(O[i][0] * inv, O[i][1] * inv, O[i][2] * inv, O[i][3] * inv);
        *(float4*)(g_seqout + (size_t)(b * CT + qi * 64 + ty * 4 + i) * CD + h * 64 + tx * 4) = o;
    }
}

// ---------------- Plucker lines ----------------
__global__ __launch_bounds__(256) void rw_lines() {
    int idx = blockIdx.x * 256 + threadIdx.x;
    if (idx >= CBT * CH) return;
    int h = idx & 15, bt = idx >> 4;
    int b = bt >> 11, t = bt & (CT - 1);
    const float* Pr = g_P + (size_t)bt * 272;
    float w1[4] = {0.f, 0.f, 0.f, 0.f}, w2[4], r1[4], r2[4];
    if (t > 0) {
        const float* Pp = g_P + (size_t)(bt - 1) * 272;
#pragma unroll
        for (int k = 0; k < 4; k++) w1[k] = Pp[h * 4 + k];
    }
#pragma unroll
    for (int k = 0; k < 4; k++) {
        w2[k] = Pr[64 + h * 4 + k];
        r1[k] = Pr[128 + h * 4 + k];
        r2[k] = Pr[192 + h * 4 + k];
    }
    float Lw[6], Lr[6];
    Lw[0] = w1[0]*w2[1] - w1[1]*w2[0]; Lw[1] = w1[0]*w2[2] - w1[2]*w2[0];
    Lw[2] = w1[0]*w2[3] - w1[3]*w2[0]; Lw[3] = w1[1]*w2[2] - w1[2]*w2[1];
    Lw[4] = w1[1]*w2[3] - w1[3]*w2[1]; Lw[5] = w1[2]*w2[3] - w1[3]*w2[2];
    Lr[0] = r1[0]*r2[1] - r1[1]*r2[0]; Lr[1] = r1[0]*r2[2] - r1[2]*r2[0];
    Lr[2] = r1[0]*r2[3] - r1[3]*r2[0]; Lr[3] = r1[1]*r2[2] - r1[2]*r2[1];
    Lr[4] = r1[1]*r2[3] - r1[3]*r2[1]; Lr[5] = r1[2]*r2[3] - r1[3]*r2[2];
    float nw = 0.f, nr = 0.f;
#pragma unroll
    for (int k = 0; k < 6; k++) { nw += Lw[k]*Lw[k]; nr += Lr[k]*Lr[k]; }
    float iw = 1.f / fmaxf(sqrtf(nw), 1e-12f);
    float ir = 1.f / fmaxf(sqrtf(nr), 1e-12f);
#pragma unroll
    for (int k = 0; k < 6; k++) { Lw[k] *= iw; Lr[k] *= ir; }
    int bh = b * CH + h;
    size_t base = ((size_t)bh * CT + t) * 6;
    g_Jw[base+0] =  Lw[5]; g_Jw[base+1] = -Lw[4]; g_Jw[base+2] = Lw[3];
    g_Jw[base+3] =  Lw[2]; g_Jw[base+4] = -Lw[1]; g_Jw[base+5] = Lw[0];
    g_Jr[base+0] =  Lr[5]; g_Jr[base+1] = -Lr[4]; g_Jr[base+2] = Lr[3];
    g_Jr[base+3] =  Lr[2]; g_Jr[base+4] = -Lr[1]; g_Jr[base+5] = Lr[0];
#pragma unroll
    for (int k = 0; k < 6; k++) g_rd[base + k] = Lr[k];
}

// ---------------- scans ----------------
__global__ __launch_bounds__(128) void rw_scanA(const float* __restrict__ decay_logits) {
    const int bh = blockIdx.x, c = blockIdx.y, h = bh & 15, t = threadIdx.x;
    const float dec = 1.f / (1.f + expf(-decay_logits[h]));
    __shared__ float sw[CLEN][6], sr[CLEN][6], sa[CLEN][6];
    __shared__ float sred[42];
    size_t base = ((size_t)bh * CT + c * CLEN + t) * 6;
#pragma unroll
    for (int k = 0; k < 6; k++) {
        sw[t][k] = g_Jw[base + k]; sr[t][k] = g_Jr[base + k]; sa[t][k] = g_rd[base + k];
    }
    if (t < 42) sred[t] = 0.f;
    __syncthreads();
    float aw[6], ar[6], cw[6], cr[6];
#pragma unroll
    for (int k = 0; k < 6; k++) { aw[k] = sa[t][k]; ar[k] = sw[t][k]; cw[k] = sw[t][k]; cr[k] = sr[t][k]; }
    float accw = 0.f, accr = 0.f, wgt = dec;
    for (int s = t - 1; s >= 0; s--) {
        float dw = 0.f, dr = 0.f;
#pragma unroll
        for (int k = 0; k < 6; k++) { dw += aw[k] * sw[s][k]; dr += ar[k] * sr[s][k]; }
        accw += wgt * dw * dw; accr += wgt * dr * dr; wgt *= dec;
    }
    g_intraw[bh * CT + c * CLEN + t] = accw;
    g_intrar[bh * CT + c * CLEN + t] = accr;
    float wl = expf(logf(dec) * (float)(CLEN - t));
    float redw[21], redr[21];
    {
        int e = 0;
#pragma unroll
        for (int i = 0; i < 6; i++)
#pragma unroll
            for (int jj = i; jj < 6; jj++) {
                redw[e] = wl * cw[i] * cw[jj]; redr[e] = wl * cr[i] * cr[jj]; e++;
            }
    }
#pragma unroll
    for (int e = 0; e < 21; e++) {
        float vw = redw[e], vr = redr[e];
#pragma unroll
        for (int msk = 16; msk; msk >>= 1) {
            vw += __shfl_xor_sync(0xffffffffu, vw, msk);
            vr += __shfl_xor_sync(0xffffffffu, vr, msk);
        }
        if ((t & 31) == 0) { atomicAdd(&sred[e], vw); atomicAdd(&sred[21 + e], vr); }
    }
    __syncthreads();
    if (t < 42) g_L[((size_t)bh * NCH + c) * 42 + t] = sred[t];
}

__global__ void rw_scanB(const float* __restrict__ decay_logits) {
    int bh = blockIdx.x, e = threadIdx.x;
    if (e >= 42) return;
    float dec = 1.f / (1.f + expf(-decay_logits[bh & 15]));
    float dC = expf(logf(dec) * (float)CLEN);
    float M = 0.f;
    for (int c = 0; c < NCH; c++) {
        g_Ms[((size_t)bh * NCH + c) * 42 + e] = M;
        M = dC * M + g_L[((size_t)bh * NCH + c) * 42 + e];
    }
}

__global__ __launch_bounds__(128) void rw_scanC(const float* __restrict__ decay_logits,
                                                const float* __restrict__ rw_mix) {
    int bh = blockIdx.x, c = blockIdx.y, t = threadIdx.x, h = bh & 15;
    float dec = 1.f / (1.f + expf(-decay_logits[h]));
    float alpha = 1.f / (1.f + expf(-rw_mix[0]));
    __shared__ float sM[42];
    if (t < 42) sM[t] = g_Ms[((size_t)bh * NCH + c) * 42 + t];
    __syncthreads();
    int tt = c * CLEN + t;
    size_t base = ((size_t)bh * CT + tt) * 6;
    float aw[6], ar[6];
#pragma unroll
    for (int k = 0; k < 6; k++) { aw[k] = g_rd[base + k]; ar[k] = g_Jw[base + k]; }
    float qw = 0.f, qr = 0.f;
    {
        int e = 0;
#pragma unroll
        for (int i = 0; i < 6; i++)
#pragma unroll
            for (int jj = i; jj < 6; jj++) {
                float f = (i == jj) ? 1.f : 2.f;
                qw += f * sM[e] * aw[i] * aw[jj];
                qr += f * sM[21 + e] * ar[i] * ar[jj];
                e++;
            }
    }
    float dp = expf(logf(dec) * (float)t);
    float scw = g_intraw[bh * CT + tt] + dp * qw;
    float scr = g_intrar[bh * CT + tt] + dp * qr;
    g_score[bh * CT + tt] = (1.f - alpha) * scw + alpha * scr;
}

__global__ void rw_gate(const float* __restrict__ mem_scale, const float* __restrict__ memg_b) {
    int bt = blockIdx.x * 256 + threadIdx.x;
    if (bt >= CBT) return;
    int b = bt >> 11, t = bt & (CT - 1);
    float s = 0.f;
#pragma unroll
    for (int h = 0; h < CH; h++) {
        float ms = g_score[(b * CH + h) * CT + t];
        float gp = g_P[(size_t)bt * 272 + 256 + h] + memg_b[h];
        s += sigf(ms * mem_scale[h]) * sigf(gp);
    }
    g_gated[bt] = s * (1.f / 16.f);
}

// ---------------- launch ----------------
extern "C" void kernel_launch(void* const* d_in, const int* in_sizes, int n_in,
                              void* d_out, int out_size) {
    (void)in_sizes; (void)n_in; (void)out_size;
    const float* x            = (const float*)d_in[0];
    const float* qkv_w        = (const float*)d_in[1];
    const float* qkv_b        = (const float*)d_in[2];
    const float* w1w          = (const float*)d_in[3];
    const float* w2w          = (const float*)d_in[4];
    const float* w1r          = (const float*)d_in[5];
    const float* w2r          = (const float*)d_in[6];
    const float* memv_w       = (const float*)d_in[7];
    const float* memv_b       = (const float*)d_in[8];
    const float* memg_w       = (const float*)d_in[9];
    const float* memg_b       = (const float*)d_in[10];
    const float* mem_scale    = (const float*)d_in[11];
    const float* rw_mix       = (const float*)d_in[12];
    const float* out_w        = (const float*)d_in[13];
    const float* out_b        = (const float*)d_in[14];
    const float* decay_logits = (const float*)d_in[15];

    float *p_qkv, *p_seq, *p_z, *p_P, *p_sw, *p_gated;
    cudaGetSymbolAddress((void**)&p_qkv,   g_qkv);
    cudaGetSymbolAddress((void**)&p_seq,   g_seqout);
    cudaGetSymbolAddress((void**)&p_z,     g_z);
    cudaGetSymbolAddress((void**)&p_P,     g_P);
    cudaGetSymbolAddress((void**)&p_sw,    g_smallW);
    cudaGetSymbolAddress((void**)&p_gated, g_gated);
    __nv_bfloat16 *p_xh, *p_xl, *p_zh, *p_zl, *p_wqh, *p_wql, *p_wvh, *p_wvl, *p_woh, *p_wol;
    cudaGetSymbolAddress((void**)&p_xh, g_xh);   cudaGetSymbolAddress((void**)&p_xl, g_xl);
    cudaGetSymbolAddress((void**)&p_zh, g_zh);   cudaGetSymbolAddress((void**)&p_zl, g_zl);
    cudaGetSymbolAddress((void**)&p_wqh, g_wqh); cudaGetSymbolAddress((void**)&p_wql, g_wql);
    cudaGetSymbolAddress((void**)&p_wvh, g_wvh); cudaGetSymbolAddress((void**)&p_wvl, g_wvl);
    cudaGetSymbolAddress((void**)&p_woh, g_woh); cudaGetSymbolAddress((void**)&p_wol, g_wol);

    cudaFuncSetAttribute(rw_gemm_mma, cudaFuncAttributeMaxDynamicSharedMemorySize, 65536);

    rw_concat_w<<<(CD * 272 + 255) / 256, 256>>>(w1w, w2w, w1r, w2r, memg_w);
    rw_gemm<<<dim3(5, CBT / 128), 256>>>(x, CD, p_sw, 272, p_P, 272, 272);
    rw_split<<<(CBT * CD + 255) / 256, 256>>>(x, p_xh, p_xl, CBT * CD);
    rw_splitT<<<dim3(QKVLD / 32, CD / 32), dim3(32, 8)>>>(qkv_w, p_wqh, p_wql, QKVLD);
    rw_splitT<<<dim3(CD / 32, CD / 32), dim3(32, 8)>>>(memv_w, p_wvh, p_wvl, CD);
    rw_splitT<<<dim3(CD / 32, CD / 32), dim3(32, 8)>>>(out_w, p_woh, p_wol, CD);
    rw_gemm_mma<<<dim3(QKVLD / 128, CBT / 128), 256, 65536>>>(
        p_xh, p_xl, p_wqh, p_wql, qkv_b, p_qkv, QKVLD, 0, nullptr, nullptr);
    rw_attn<<<dim3(CT / 64, NBH), 256>>>();
    rw_lines<<<(CBT * CH + 255) / 256, 256>>>();
    rw_scanA<<<dim3(NBH, NCH), 128>>>(decay_logits);
    rw_scanB<<<NBH, 64>>>(decay_logits);
    rw_scanC<<<dim3(NBH, NCH), 128>>>(decay_logits, rw_mix);
    rw_gate<<<(CBT + 255) / 256, 256>>>(mem_scale, memg_b);
    rw_gemm_mma<<<dim3(CD / 128, CBT / 128), 256, 65536>>>(
        p_xh, p_xl, p_wvh, p_wvl, memv_b, p_z, CD, 1, p_seq, p_gated);
    rw_split<<<(CBT * CD + 255) / 256, 256>>>(p_z, p_zh, p_zl, CBT * CD);
    rw_gemm_mma<<<dim3(CD / 128, CBT / 128), 256, 65536>>>(
        p_zh, p_zl, p_woh, p_wol, out_b, (float*)d_out, CD, 0, nullptr, nullptr);
}

// round 16
// speedup vs baseline: 2.5227x; 1.6611x over previous
#include <cuda_runtime.h>
#include <cuda_bf16.h>
#include <math.h>
#include <stdint.h>

#define CB 2
#define CT 2048
#define CD 1024
#define CH 16
#define CBT 4096
#define QKVLD 3072
#define NBH 32
#define NCH 16
#define CLEN 128

__device__ float g_qkv[(size_t)CBT * QKVLD];
__device__ float g_seqout[(size_t)CBT * CD];
__device__ float g_z[(size_t)CBT * CD];
__device__ float g_P[(size_t)CBT * 272];
__device__ float g_smallW[(size_t)CD * 272];
__device__ float g_Jw[NBH * CT * 6];
__device__ float g_Jr[NBH * CT * 6];
__device__ float g_rd[NBH * CT * 6];
__device__ float g_intraw[NBH * CT];
__device__ float g_intrar[NBH * CT];
__device__ float g_L[NBH * NCH * 42];
__device__ float g_Ms[NBH * NCH * 42];
__device__ float g_score[NBH * CT];
__device__ float g_gated[CBT];

__device__ __align__(16) __nv_bfloat16 g_xh[(size_t)CBT * CD];
__device__ __align__(16) __nv_bfloat16 g_xl[(size_t)CBT * CD];
__device__ __align__(16) __nv_bfloat16 g_zh[(size_t)CBT * CD];
__device__ __align__(16) __nv_bfloat16 g_zl[(size_t)CBT * CD];
__device__ __align__(16) __nv_bfloat16 g_wqh[(size_t)QKVLD * CD];
__device__ __align__(16) __nv_bfloat16 g_wql[(size_t)QKVLD * CD];
__device__ __align__(16) __nv_bfloat16 g_wvh[(size_t)CD * CD];
__device__ __align__(16) __nv_bfloat16 g_wvl[(size_t)CD * CD];
__device__ __align__(16) __nv_bfloat16 g_woh[(size_t)CD * CD];
__device__ __align__(16) __nv_bfloat16 g_wol[(size_t)CD * CD];

// attention bf16 split buffers, [bh][T][64] layout
__device__ __align__(16) __nv_bfloat16 g_aqh[(size_t)CBT * CD];
__device__ __align__(16) __nv_bfloat16 g_aql[(size_t)CBT * CD];
__device__ __align__(16) __nv_bfloat16 g_akh[(size_t)CBT * CD];
__device__ __align__(16) __nv_bfloat16 g_akl[(size_t)CBT * CD];
__device__ __align__(16) __nv_bfloat16 g_avh[(size_t)CBT * CD];
__device__ __align__(16) __nv_bfloat16 g_avl[(size_t)CBT * CD];

__device__ __forceinline__ float sigf(float x) { return 1.f / (1.f + __expf(-x)); }

__device__ __forceinline__ uint32_t s2u(const void* p) {
    uint32_t a;
    asm("{ .reg .u64 t; cvta.to.shared.u64 t, %1; cvt.u32.u64 %0, t; }" : "=r"(a) : "l"(p));
    return a;
}

// ===================== baseline-PTX tensor-core primitives =====================
#define LDMX4(r, a) asm volatile( \
    "ldmatrix.sync.aligned.m8n8.x4.shared.b16 {%0,%1,%2,%3}, [%4];" \
    : "=r"((r)[0]), "=r"((r)[1]), "=r"((r)[2]), "=r"((r)[3]) : "r"(a))

#define LDMX4T(r, a) asm volatile( \
    "ldmatrix.sync.aligned.m8n8.x4.trans.shared.b16 {%0,%1,%2,%3}, [%4];" \
    : "=r"((r)[0]), "=r"((r)[1]), "=r"((r)[2]), "=r"((r)[3]) : "r"(a))

#define MMA16816(c, a, b0, b1) asm volatile( \
    "mma.sync.aligned.m16n8k16.row.col.f32.bf16.bf16.f32 " \
    "{%0,%1,%2,%3}, {%4,%5,%6,%7}, {%8,%9}, {%0,%1,%2,%3};" \
    : "+f"((c)[0]), "+f"((c)[1]), "+f"((c)[2]), "+f"((c)[3]) \
    : "r"((a)[0]), "r"((a)[1]), "r"((a)[2]), "r"((a)[3]), "r"(b0), "r"(b1))

#define CPA(dst, src) asm volatile("cp.async.cg.shared.global [%0], [%1], 16;" :: "r"(dst), "l"(src))
#define CPC() asm volatile("cp.async.commit_group;" ::: "memory")
#define CPW(n) asm volatile("cp.async.wait_group %0;" :: "n"(n) : "memory")
#define SWZ(b) ((b) ^ (((b) >> 3) & 0x30))

// ---------------- split / transpose-split ----------------
__global__ void rw_split(const float* __restrict__ in, __nv_bfloat16* __restrict__ hi,
                         __nv_bfloat16* __restrict__ lo, int n) {
    int i = blockIdx.x * 256 + threadIdx.x;
    if (i >= n) return;
    float v = in[i];
    __nv_bfloat16 h = __float2bfloat16(v);
    hi[i] = h;
    lo[i] = __float2bfloat16(v - __bfloat162float(h));
}

__global__ void rw_splitT(const float* __restrict__ W, __nv_bfloat16* __restrict__ Th,
                          __nv_bfloat16* __restrict__ Tl, int N) {
    __shared__ float t[32][33];
    int n0 = blockIdx.x * 32, k0 = blockIdx.y * 32;
    for (int i = threadIdx.y; i < 32; i += 8)
        t[i][threadIdx.x] = W[(size_t)(k0 + i) * N + n0 + threadIdx.x];
    __syncthreads();
    for (int i = threadIdx.y; i < 32; i += 8) {
        float v = t[threadIdx.x][i];
        __nv_bfloat16 h = __float2bfloat16(v);
        size_t o = (size_t)(n0 + i) * CD + k0 + threadIdx.x;
        Th[o] = h;
        Tl[o] = __float2bfloat16(v - __bfloat162float(h));
    }
}

// ---------------- split qkv -> per-(b,h) bf16 hi/lo; Q pre-scaled ----------------
__global__ void rw_splitqkv() {
    int i = blockIdx.x * 256 + threadIdx.x;
    if (i >= CBT * CD / 2) return;
    int d2 = i & 31;
    int h = (i >> 5) & 15;
    int bt = i >> 9;
    int t = bt & (CT - 1), b = bt >> 11;
    const float2* src = (const float2*)(g_qkv + (size_t)bt * QKVLD + h * 64) + d2;
    size_t dst = ((size_t)(b * CH + h) * CT + t) * 32 + d2;
    float2 q = src[0], k = src[512], v = src[1024];
    q.x *= 0.125f; q.y *= 0.125f;
    __nv_bfloat162 qh = __floats2bfloat162_rn(q.x, q.y);
    __nv_bfloat162 ql = __floats2bfloat162_rn(q.x - __bfloat162float(qh.x), q.y - __bfloat162float(qh.y));
    __nv_bfloat162 kh = __floats2bfloat162_rn(k.x, k.y);
    __nv_bfloat162 kl = __floats2bfloat162_rn(k.x - __bfloat162float(kh.x), k.y - __bfloat162float(kh.y));
    __nv_bfloat162 vh = __floats2bfloat162_rn(v.x, v.y);
    __nv_bfloat162 vl = __floats2bfloat162_rn(v.x - __bfloat162float(vh.x), v.y - __bfloat162float(vh.y));
    ((__nv_bfloat162*)g_aqh)[dst] = qh; ((__nv_bfloat162*)g_aql)[dst] = ql;
    ((__nv_bfloat162*)g_akh)[dst] = kh; ((__nv_bfloat162*)g_akl)[dst] = kl;
    ((__nv_bfloat162*)g_avh)[dst] = vh; ((__nv_bfloat162*)g_avl)[dst] = vl;
}

// ---------------- tensor-core flash attention ----------------
// grid (16 qtiles, 32 bh), 256 threads. Q-tile 128 x K-tile 64, warp = m16 x n64.
// smem: Qh 16K | Ql 16K | 2 stages x (Kh 8K | Kl 8K | Vh 8K | Vl 8K) = 96KB.
__global__ __launch_bounds__(256) void rw_attn_mma() {
    extern __shared__ __align__(16) char smem[];
    const int tid = threadIdx.x, lane = tid & 31, wid = tid >> 5;
    const int qi = blockIdx.x, bh = blockIdx.y;
    const int b = bh >> 4, h = bh & 15;
    const uint32_t S = s2u(smem);
    const uint32_t Qh_ = S, Ql_ = S + 16384;

    const __nv_bfloat16* gqh = g_aqh + ((size_t)bh * CT + qi * 128) * 64;
    const __nv_bfloat16* gql = g_aql + ((size_t)bh * CT + qi * 128) * 64;
    const __nv_bfloat16* gkh = g_akh + (size_t)bh * CT * 64;
    const __nv_bfloat16* gkl = g_akl + (size_t)bh * CT * 64;
    const __nv_bfloat16* gvh = g_avh + (size_t)bh * CT * 64;
    const __nv_bfloat16* gvl = g_avl + (size_t)bh * CT * 64;

    // load Q (once)
#pragma unroll
    for (int it = 0; it < 4; it++) {
        int idx = tid + it * 256, r = idx >> 3, cg = idx & 7;
        uint32_t off = SWZ((uint32_t)(r * 128 + cg * 16));
        CPA(Qh_ + off, (const char*)(gqh + r * 64 + cg * 8));
        CPA(Ql_ + off, (const char*)(gql + r * 64 + cg * 8));
    }
#define LOADKV(j, p) do { \
    uint32_t _kb = S + 32768 + (p) * 32768; \
    _Pragma("unroll") \
    for (int it = 0; it < 2; it++) { \
        int idx = tid + it * 256, r = idx >> 3, cg = idx & 7; \
        uint32_t off = SWZ((uint32_t)(r * 128 + cg * 16)); \
        size_t go = (size_t)((j) * 64 + r) * 64 + cg * 8; \
        CPA(_kb + off,         (const char*)(gkh + go)); \
        CPA(_kb + 8192 + off,  (const char*)(gkl + go)); \
        CPA(_kb + 16384 + off, (const char*)(gvh + go)); \
        CPA(_kb + 24576 + off, (const char*)(gvl + go)); \
    } \
} while (0)

    LOADKV(0, 0);
    CPC();

    float accO[8][4];
#pragma unroll
    for (int i = 0; i < 8; i++)
#pragma unroll
        for (int e = 0; e < 4; e++) accO[i][e] = 0.f;
    float m0 = -1e30f, m1 = -1e30f, l0 = 0.f, l1 = 0.f;

    const int jmax = 2 * qi + 2;
    for (int j = 0; j < jmax; j++) {
        const int p = j & 1;
        if (j + 1 < jmax) { LOADKV(j + 1, p ^ 1); CPC(); CPW(1); }
        else CPW(0);
        __syncthreads();
        const uint32_t Kh_ = S + 32768 + p * 32768;
        const uint32_t Kl_ = Kh_ + 8192, Vh_ = Kh_ + 16384, Vl_ = Kh_ + 24576;

        // ---- S = Q K^T (3-term split) ----
        float accS[8][4];
#pragma unroll
        for (int i = 0; i < 8; i++)
#pragma unroll
            for (int e = 0; e < 4; e++) accS[i][e] = 0.f;
#pragma unroll
        for (int ks = 0; ks < 4; ks++) {
            uint32_t aqh[4], aql[4];
            {
                int r = wid * 16 + (lane & 15);
                int g = ks * 2 + (lane >> 4);
                uint32_t off = SWZ((uint32_t)(r * 128 + g * 16));
                LDMX4(aqh, Qh_ + off);
                LDMX4(aql, Ql_ + off);
            }
#pragma unroll
            for (int t = 0; t < 4; t++) {
                uint32_t bkh[4], bkl[4];
                int n = t * 16 + (lane & 7) + ((lane >> 4) << 3);
                int g = ks * 2 + ((lane >> 3) & 1);
                uint32_t off = SWZ((uint32_t)(n * 128 + g * 16));
                LDMX4(bkh, Kh_ + off);
                LDMX4(bkl, Kl_ + off);
                MMA16816(accS[t * 2], aqh, bkh[0], bkh[1]);
                MMA16816(accS[t * 2], aql, bkh[0], bkh[1]);
                MMA16816(accS[t * 2], aqh, bkl[0], bkl[1]);
                MMA16816(accS[t * 2 + 1], aqh, bkh[2], bkh[3]);
                MMA16816(accS[t * 2 + 1], aql, bkh[2], bkh[3]);
                MMA16816(accS[t * 2 + 1], aqh, bkl[2], bkl[3]);
            }
        }
        // ---- causal mask (only last two tiles can cross the diagonal) ----
        if (j >= 2 * qi) {
            int r0 = qi * 128 + wid * 16 + (lane >> 2);
#pragma unroll
            for (int jn = 0; jn < 8; jn++) {
                int col = j * 64 + jn * 8 + (lane & 3) * 2;
                if (col > r0)         accS[jn][0] = -1e30f;
                if (col + 1 > r0)     accS[jn][1] = -1e30f;
                if (col > r0 + 8)     accS[jn][2] = -1e30f;
                if (col + 1 > r0 + 8) accS[jn][3] = -1e30f;
            }
        }
        // ---- online softmax (per-warp rows; quad shuffle only) ----
        float ml0 = -1e30f, ml1 = -1e30f;
#pragma unroll
        for (int jn = 0; jn < 8; jn++) {
            ml0 = fmaxf(ml0, fmaxf(accS[jn][0], accS[jn][1]));
            ml1 = fmaxf(ml1, fmaxf(accS[jn][2], accS[jn][3]));
        }
#pragma unroll
        for (int msk = 1; msk <= 2; msk <<= 1) {
            ml0 = fmaxf(ml0, __shfl_xor_sync(0xffffffffu, ml0, msk));
            ml1 = fmaxf(ml1, __shfl_xor_sync(0xffffffffu, ml1, msk));
        }
        float mn0 = fmaxf(m0, ml0), mn1 = fmaxf(m1, ml1);
        float c0 = __expf(m0 - mn0), c1 = __expf(m1 - mn1);
        m0 = mn0; m1 = mn1;
        float s0 = 0.f, s1 = 0.f;
        uint32_t ph[4][4], pl[4][4];
#pragma unroll
        for (int ks = 0; ks < 4; ks++)
#pragma unroll
            for (int u = 0; u < 2; u++) {
                int jn = ks * 2 + u;
                float p0 = __expf(accS[jn][0] - mn0);
                float p1 = __expf(accS[jn][1] - mn0);
                float p2 = __expf(accS[jn][2] - mn1);
                float p3 = __expf(accS[jn][3] - mn1);
                s0 += p0 + p1; s1 += p2 + p3;
                __nv_bfloat162 h01 = __floats2bfloat162_rn(p0, p1);
                __nv_bfloat162 h23 = __floats2bfloat162_rn(p2, p3);
                __nv_bfloat162 l01 = __floats2bfloat162_rn(p0 - __bfloat162float(h01.x),
                                                           p1 - __bfloat162float(h01.y));
                __nv_bfloat162 l23 = __floats2bfloat162_rn(p2 - __bfloat162float(h23.x),
                                                           p3 - __bfloat162float(h23.y));
                ph[ks][u * 2]     = *(uint32_t*)&h01;
                ph[ks][u * 2 + 1] = *(uint32_t*)&h23;
                pl[ks][u * 2]     = *(uint32_t*)&l01;
                pl[ks][u * 2 + 1] = *(uint32_t*)&l23;
            }
#pragma unroll
        for (int msk = 1; msk <= 2; msk <<= 1) {
            s0 += __shfl_xor_sync(0xffffffffu, s0, msk);
            s1 += __shfl_xor_sync(0xffffffffu, s1, msk);
        }
        l0 = l0 * c0 + s0;
        l1 = l1 * c1 + s1;
#pragma unroll
        for (int jo = 0; jo < 8; jo++) {
            accO[jo][0] *= c0; accO[jo][1] *= c0;
            accO[jo][2] *= c1; accO[jo][3] *= c1;
        }
        // ---- O += P V (3-term split), B frags via trans ldmatrix ----
#pragma unroll
        for (int ks = 0; ks < 4; ks++)
#pragma unroll
            for (int t = 0; t < 4; t++) {
                uint32_t bvh[4], bvl[4];
                int r = ks * 16 + (lane & 15);
                int cb = t * 32 + (lane >> 4) * 16;
                uint32_t off = SWZ((uint32_t)(r * 128 + cb));
                LDMX4T(bvh, Vh_ + off);
                LDMX4T(bvl, Vl_ + off);
                MMA16816(accO[t * 2], ph[ks], bvh[0], bvh[1]);
                MMA16816(accO[t * 2], pl[ks], bvh[0], bvh[1]);
                MMA16816(accO[t * 2], ph[ks], bvl[0], bvl[1]);
                MMA16816(accO[t * 2 + 1], ph[ks], bvh[2], bvh[3]);
                MMA16816(accO[t * 2 + 1], pl[ks], bvh[2], bvh[3]);
                MMA16816(accO[t * 2 + 1], ph[ks], bvl[2], bvl[3]);
            }
        __syncthreads();
    }
#undef LOADKV

    float inv0 = 1.f / l0, inv1 = 1.f / l1;
    int r0 = qi * 128 + wid * 16 + (lane >> 2);
    int cc = (lane & 3) * 2;
#pragma unroll
    for (int jo = 0; jo < 8; jo++) {
        int d = jo * 8 + cc;
        float* o0 = g_seqout + (size_t)(b * CT + r0) * CD + h * 64 + d;
        float* o1 = g_seqout + (size_t)(b * CT + r0 + 8) * CD + h * 64 + d;
        o0[0] = accO[jo][0] * inv0; o0[1] = accO[jo][1] * inv0;
        o1[0] = accO[jo][2] * inv1; o1[1] = accO[jo][3] * inv1;
    }
}

// ---------------- split-bf16 tensor-core GEMM (proven in R14) ----------------
__global__ __launch_bounds__(256) void rw_gemm_mma(
    const __nv_bfloat16* __restrict__ Ah, const __nv_bfloat16* __restrict__ Al,
    const __nv_bfloat16* __restrict__ Bh, const __nv_bfloat16* __restrict__ Bl,
    const float* __restrict__ bias, float* __restrict__ C, int N, int mode,
    const float* __restrict__ seqout, const float* __restrict__ gated) {
    extern __shared__ __align__(16) char smem[];
    const int tid = threadIdx.x;
    const int lane = tid & 31, wid = tid >> 5;
    const int wm = wid >> 2, wn = wid & 3;
    const int m0 = blockIdx.y * 128, n0 = blockIdx.x * 128;
    const uint32_t sb0 = s2u(smem);

    float acc[4][4][4];
#pragma unroll
    for (int i = 0; i < 4; i++)
#pragma unroll
        for (int j = 0; j < 4; j++)
#pragma unroll
            for (int k = 0; k < 4; k++) acc[i][j][k] = 0.f;

    const __nv_bfloat16* gAh = Ah + (size_t)m0 * CD;
    const __nv_bfloat16* gAl = Al + (size_t)m0 * CD;
    const __nv_bfloat16* gBh = Bh + (size_t)n0 * CD;
    const __nv_bfloat16* gBl = Bl + (size_t)n0 * CD;

    const int r_ld = tid >> 2, g_ld = tid & 3;
    const uint32_t sw0 = SWZ((uint32_t)(r_ld * 64 + g_ld * 16));
    const uint32_t sw1 = SWZ((uint32_t)((r_ld + 64) * 64 + g_ld * 16));
    const size_t go0 = (size_t)r_ld * CD + g_ld * 8;
    const size_t go1 = (size_t)(r_ld + 64) * CD + g_ld * 8;

#define LOADCH(ch, p) do { \
    int _kc = (ch) * 32; \
    uint32_t _sb = sb0 + (p) * 32768; \
    CPA(_sb + sw0,         (const char*)(gAh + go0 + _kc)); \
    CPA(_sb + sw1,         (const char*)(gAh + go1 + _kc)); \
    CPA(_sb + 8192 + sw0,  (const char*)(gAl + go0 + _kc)); \
    CPA(_sb + 8192 + sw1,  (const char*)(gAl + go1 + _kc)); \
    CPA(_sb + 16384 + sw0, (const char*)(gBh + go0 + _kc)); \
    CPA(_sb + 16384 + sw1, (const char*)(gBh + go1 + _kc)); \
    CPA(_sb + 24576 + sw0, (const char*)(gBl + go0 + _kc)); \
    CPA(_sb + 24576 + sw1, (const char*)(gBl + go1 + _kc)); \
    CPC(); \
} while (0)

    LOADCH(0, 0);
    for (int ch = 0; ch < 32; ch++) {
        const int p = ch & 1;
        if (ch + 1 < 32) { LOADCH(ch + 1, p ^ 1); CPW(1); }
        else             { CPW(0); }
        __syncthreads();
        const uint32_t sb = sb0 + p * 32768;
#pragma unroll
        for (int kk = 0; kk < 32; kk += 16) {
            uint32_t bh[2][4], bl[2][4], af[4][4];
#pragma unroll
            for (int j = 0; j < 2; j++) {
                int n = wn * 32 + j * 16 + (lane & 7) + ((lane >> 4) << 3);
                int g = (kk >> 3) + ((lane >> 3) & 1);
                uint32_t ad = sb + 16384 + SWZ((uint32_t)(n * 64 + g * 16));
                LDMX4(bh[j], ad);
                LDMX4(bl[j], ad + 8192);
            }
#pragma unroll
            for (int i = 0; i < 4; i++) {
                int r = wm * 64 + i * 16 + (lane & 15);
                int g = (kk >> 3) + (lane >> 4);
                uint32_t ad = sb + SWZ((uint32_t)(r * 64 + g * 16));
                LDMX4(af[i], ad);
            }
#pragma unroll
            for (int i = 0; i < 4; i++)
#pragma unroll
                for (int j = 0; j < 4; j++) {
                    MMA16816(acc[i][j], af[i], bh[j >> 1][(j & 1) * 2], bh[j >> 1][(j & 1) * 2 + 1]);
                    MMA16816(acc[i][j], af[i], bl[j >> 1][(j & 1) * 2], bl[j >> 1][(j & 1) * 2 + 1]);
                }
#pragma unroll
            for (int i = 0; i < 4; i++) {
                int r = wm * 64 + i * 16 + (lane & 15);
                int g = (kk >> 3) + (lane >> 4);
                uint32_t ad = sb + 8192 + SWZ((uint32_t)(r * 64 + g * 16));
                LDMX4(af[i], ad);
            }
#pragma unroll
            for (int i = 0; i < 4; i++)
#pragma unroll
                for (int j = 0; j < 4; j++)
                    MMA16816(acc[i][j], af[i], bh[j >> 1][(j & 1) * 2], bh[j >> 1][(j & 1) * 2 + 1]);
        }
        __syncthreads();
    }
#undef LOADCH

    const int mb = m0 + wm * 64, nb = n0 + wn * 32;
    const int rr = lane >> 2, cc = (lane & 3) * 2;
#pragma unroll
    for (int i = 0; i < 4; i++) {
        int r0 = mb + i * 16 + rr;
        int r1 = r0 + 8;
        float g0 = 0.f, g1 = 0.f;
        if (mode) { g0 = gated[r0]; g1 = gated[r1]; }
#pragma unroll
        for (int j = 0; j < 4; j++) {
            int col = nb + j * 8 + cc;
            float b0 = bias[col], b1 = bias[col + 1];
            float v0 = acc[i][j][0] + b0, v1 = acc[i][j][1] + b1;
            float v2 = acc[i][j][2] + b0, v3 = acc[i][j][3] + b1;
            if (mode) {
                v0 = seqout[(size_t)r0 * CD + col]     + g0 * v0;
                v1 = seqout[(size_t)r0 * CD + col + 1] + g0 * v1;
                v2 = seqout[(size_t)r1 * CD + col]     + g1 * v2;
                v3 = seqout[(size_t)r1 * CD + col + 1] + g1 * v3;
            }
            *(float2*)(C + (size_t)r0 * N + col) = make_float2(v0, v1);
            *(float2*)(C + (size_t)r1 * N + col) = make_float2(v2, v3);
        }
    }
}

// ---------------- small-weight concat ----------------
__global__ void rw_concat_w(const float* __restrict__ w1w, const float* __restrict__ w2w,
                            const float* __restrict__ w1r, const float* __restrict__ w2r,
                            const float* __restrict__ memg) {
    int i = blockIdx.x * 256 + threadIdx.x;
    if (i >= CD * 272) return;
    int k = i / 272, n = i % 272;
    float v;
    if (n < 64)       v = w1w[k * 64 + n];
    else if (n < 128) v = w2w[k * 64 + (n - 64)];
    else if (n < 192) v = w1r[k * 64 + (n - 128)];
    else if (n < 256) v = w2r[k * 64 + (n - 192)];
    else              v = memg[k * 16 + (n - 256)];
    g_smallW[i] = v;
}

// ---------------- fp32 GEMM (small projections only) ----------------
__global__ __launch_bounds__(256) void rw_gemm(
    const float* __restrict__ A, int lda, const float* __restrict__ W, int ldw,
    float* __restrict__ C, int ldc, int N) {
    __shared__ float As[16][132];
    __shared__ float Bs[16][68];
    const int tid = threadIdx.x;
    const int tx = tid & 15, ty = tid >> 4;
    const int m0 = blockIdx.y * 128, n0 = blockIdx.x * 64;
    float acc[8][4];
#pragma unroll
    for (int i = 0; i < 8; i++)
#pragma unroll
        for (int j = 0; j < 4; j++) acc[i][j] = 0.f;
    for (int k0 = 0; k0 < CD; k0 += 16) {
#pragma unroll
        for (int u = 0; u < 2; u++) {
            int idx = tid + u * 256, row = idx >> 2, kk = (idx & 3) << 2;
            float4 v = *(const float4*)(A + (size_t)(m0 + row) * lda + k0 + kk);
            As[kk][row] = v.x; As[kk + 1][row] = v.y; As[kk + 2][row] = v.z; As[kk + 3][row] = v.w;
        }
        {
            int kk = tid >> 4, j = (tid & 15) << 2;
            float4 v = make_float4(0.f, 0.f, 0.f, 0.f);
            if (n0 + j < N) v = *(const float4*)(W + (size_t)(k0 + kk) * ldw + n0 + j);
            *(float4*)&Bs[kk][j] = v;
        }
        __syncthreads();
#pragma unroll
        for (int kk = 0; kk < 16; kk++) {
            float4 a0 = *(const float4*)&As[kk][ty * 8];
            float4 a1 = *(const float4*)&As[kk][ty * 8 + 4];
            float4 b = *(const float4*)&Bs[kk][tx * 4];
            float av[8] = {a0.x, a0.y, a0.z, a0.w, a1.x, a1.y, a1.z, a1.w};
            float bv[4] = {b.x, b.y, b.z, b.w};
#pragma unroll
            for (int i = 0; i < 8; i++)
#pragma unroll
                for (int j = 0; j < 4; j++) acc[i][j] += av[i] * bv[j];
        }
        __syncthreads();
    }
#pragma unroll
    for (int i = 0; i < 8; i++) {
        int m = m0 + ty * 8 + i;
#pragma unroll
        for (int j = 0; j < 4; j++) {
            int n = n0 + tx * 4 + j;
            if (n < N) C[(size_t)m * ldc + n] = acc[i][j];
        }
    }
}

// ---------------- Plucker lines ----------------
__global__ __launch_bounds__(256) void rw_lines() {
    int idx = blockIdx.x * 256 + threadIdx.x;
    if (idx >= CBT * CH) return;
    int h = idx & 15, bt = idx >> 4;
    int b = bt >> 11, t = bt & (CT - 1);
    const float* Pr = g_P + (size_t)bt * 272;
    float w1[4] = {0.f, 0.f, 0.f, 0.f}, w2[4], r1[4], r2[4];
    if (t > 0) {
        const float* Pp = g_P + (size_t)(bt - 1) * 272;
#pragma unroll
        for (int k = 0; k < 4; k++) w1[k] = Pp[h * 4 + k];
    }
#pragma unroll
    for (int k = 0; k < 4; k++) {
        w2[k] = Pr[64 + h * 4 + k];
        r1[k] = Pr[128 + h * 4 + k];
        r2[k] = Pr[192 + h * 4 + k];
    }
    float Lw[6], Lr[6];
    Lw[0] = w1[0]*w2[1] - w1[1]*w2[0]; Lw[1] = w1[0]*w2[2] - w1[2]*w2[0];
    Lw[2] = w1[0]*w2[3] - w1[3]*w2[0]; Lw[3] = w1[1]*w2[2] - w1[2]*w2[1];
    Lw[4] = w1[1]*w2[3] - w1[3]*w2[1]; Lw[5] = w1[2]*w2[3] - w1[3]*w2[2];
    Lr[0] = r1[0]*r2[1] - r1[1]*r2[0]; Lr[1] = r1[0]*r2[2] - r1[2]*r2[0];
    Lr[2] = r1[0]*r2[3] - r1[3]*r2[0]; Lr[3] = r1[1]*r2[2] - r1[2]*r2[1];
    Lr[4] = r1[1]*r2[3] - r1[3]*r2[1]; Lr[5] = r1[2]*r2[3] - r1[3]*r2[2];
    float nw = 0.f, nr = 0.f;
#pragma unroll
    for (int k = 0; k < 6; k++) { nw += Lw[k]*Lw[k]; nr += Lr[k]*Lr[k]; }
    float iw = 1.f / fmaxf(sqrtf(nw), 1e-12f);
    float ir = 1.f / fmaxf(sqrtf(nr), 1e-12f);
#pragma unroll
    for (int k = 0; k < 6; k++) { Lw[k] *= iw; Lr[k] *= ir; }
    int bh = b * CH + h;
    size_t base = ((size_t)bh * CT + t) * 6;
    g_Jw[base+0] =  Lw[5]; g_Jw[base+1] = -Lw[4]; g_Jw[base+2] = Lw[3];
    g_Jw[base+3] =  Lw[2]; g_Jw[base+4] = -Lw[1]; g_Jw[base+5] = Lw[0];
    g_Jr[base+0] =  Lr[5]; g_Jr[base+1] = -Lr[4]; g_Jr[base+2] = Lr[3];
    g_Jr[base+3] =  Lr[2]; g_Jr[base+4] = -Lr[1]; g_Jr[base+5] = Lr[0];
#pragma unroll
    for (int k = 0; k < 6; k++) g_rd[base + k] = Lr[k];
}

// ---------------- scans ----------------
__global__ __launch_bounds__(128) void rw_scanA(const float* __restrict__ decay_logits) {
    const int bh = blockIdx.x, c = blockIdx.y, h = bh & 15, t = threadIdx.x;
    const float dec = 1.f / (1.f + expf(-decay_logits[h]));
    __shared__ float sw[CLEN][6], sr[CLEN][6], sa[CLEN][6];
    __shared__ float sred[42];
    size_t base = ((size_t)bh * CT + c * CLEN + t) * 6;
#pragma unroll
    for (int k = 0; k < 6; k++) {
        sw[t][k] = g_Jw[base + k]; sr[t][k] = g_Jr[base + k]; sa[t][k] = g_rd[base + k];
    }
    if (t < 42) sred[t] = 0.f;
    __syncthreads();
    float aw[6], ar[6], cw[6], cr[6];
#pragma unroll
    for (int k = 0; k < 6; k++) { aw[k] = sa[t][k]; ar[k] = sw[t][k]; cw[k] = sw[t][k]; cr[k] = sr[t][k]; }
    float accw = 0.f, accr = 0.f, wgt = dec;
    for (int s = t - 1; s >= 0; s--) {
        float dw = 0.f, dr = 0.f;
#pragma unroll
        for (int k = 0; k < 6; k++) { dw += aw[k] * sw[s][k]; dr += ar[k] * sr[s][k]; }
        accw += wgt * dw * dw; accr += wgt * dr * dr; wgt *= dec;
    }
    g_intraw[bh * CT + c * CLEN + t] = accw;
    g_intrar[bh * CT + c * CLEN + t] = accr;
    float wl = expf(logf(dec) * (float)(CLEN - t));
    float redw[21], redr[21];
    {
        int e = 0;
#pragma unroll
        for (int i = 0; i < 6; i++)
#pragma unroll
            for (int jj = i; jj < 6; jj++) {
                redw[e] = wl * cw[i] * cw[jj]; redr[e] = wl * cr[i] * cr[jj]; e++;
            }
    }
#pragma unroll
    for (int e = 0; e < 21; e++) {
        float vw = redw[e], vr = redr[e];
#pragma unroll
        for (int msk = 16; msk; msk >>= 1) {
            vw += __shfl_xor_sync(0xffffffffu, vw, msk);
            vr += __shfl_xor_sync(0xffffffffu, vr, msk);
        }
        if ((t & 31) == 0) { atomicAdd(&sred[e], vw); atomicAdd(&sred[21 + e], vr); }
    }
    __syncthreads();
    if (t < 42) g_L[((size_t)bh * NCH + c) * 42 + t] = sred[t];
}

__global__ void rw_scanB(const float* __restrict__ decay_logits) {
    int bh = blockIdx.x, e = threadIdx.x;
    if (e >= 42) return;
    float dec = 1.f / (1.f + expf(-decay_logits[bh & 15]));
    float dC = expf(logf(dec) * (float)CLEN);
    float M = 0.f;
    for (int c = 0; c < NCH; c++) {
        g_Ms[((size_t)bh * NCH + c) * 42 + e] = M;
        M = dC * M + g_L[((size_t)bh * NCH + c) * 42 + e];
    }
}

__global__ __launch_bounds__(128) void rw_scanC(const float* __restrict__ decay_logits,
                                                const float* __restrict__ rw_mix) {
    int bh = blockIdx.x, c = blockIdx.y, t = threadIdx.x, h = bh & 15;
    float dec = 1.f / (1.f + expf(-decay_logits[h]));
    float alpha = 1.f / (1.f + expf(-rw_mix[0]));
    __shared__ float sM[42];
    if (t < 42) sM[t] = g_Ms[((size_t)bh * NCH + c) * 42 + t];
    __syncthreads();
    int tt = c * CLEN + t;
    size_t base = ((size_t)bh * CT + tt) * 6;
    float aw[6], ar[6];
#pragma unroll
    for (int k = 0; k < 6; k++) { aw[k] = g_rd[base + k]; ar[k] = g_Jw[base + k]; }
    float qw = 0.f, qr = 0.f;
    {
        int e = 0;
#pragma unroll
        for (int i = 0; i < 6; i++)
#pragma unroll
            for (int jj = i; jj < 6; jj++) {
                float f = (i == jj) ? 1.f : 2.f;
                qw += f * sM[e] * aw[i] * aw[jj];
                qr += f * sM[21 + e] * ar[i] * ar[jj];
                e++;
            }
    }
    float dp = expf(logf(dec) * (float)t);
    float scw = g_intraw[bh * CT + tt] + dp * qw;
    float scr = g_intrar[bh * CT + tt] + dp * qr;
    g_score[bh * CT + tt] = (1.f - alpha) * scw + alpha * scr;
}

__global__ void rw_gate(const float* __restrict__ mem_scale, const float* __restrict__ memg_b) {
    int bt = blockIdx.x * 256 + threadIdx.x;
    if (bt >= CBT) return;
    int b = bt >> 11, t = bt & (CT - 1);
    float s = 0.f;
#pragma unroll
    for (int h = 0; h < CH; h++) {
        float ms = g_score[(b * CH + h) * CT + t];
        float gp = g_P[(size_t)bt * 272 + 256 + h] + memg_b[h];
        s += sigf(ms * mem_scale[h]) * sigf(gp);
    }
    g_gated[bt] = s * (1.f / 16.f);
}

// ---------------- launch ----------------
extern "C" void kernel_launch(void* const* d_in, const int* in_sizes, int n_in,
                              void* d_out, int out_size) {
    (void)in_sizes; (void)n_in; (void)out_size;
    const float* x            = (const float*)d_in[0];
    const float* qkv_w        = (const float*)d_in[1];
    const float* qkv_b        = (const float*)d_in[2];
    const float* w1w          = (const float*)d_in[3];
    const float* w2w          = (const float*)d_in[4];
    const float* w1r          = (const float*)d_in[5];
    const float* w2r          = (const float*)d_in[6];
    const float* memv_w       = (const float*)d_in[7];
    const float* memv_b       = (const float*)d_in[8];
    const float* memg_w       = (const float*)d_in[9];
    const float* memg_b       = (const float*)d_in[10];
    const float* mem_scale    = (const float*)d_in[11];
    const float* rw_mix       = (const float*)d_in[12];
    const float* out_w        = (const float*)d_in[13];
    const float* out_b        = (const float*)d_in[14];
    const float* decay_logits = (const float*)d_in[15];

    float *p_qkv, *p_seq, *p_z, *p_P, *p_sw, *p_gated;
    cudaGetSymbolAddress((void**)&p_qkv,   g_qkv);
    cudaGetSymbolAddress((void**)&p_seq,   g_seqout);
    cudaGetSymbolAddress((void**)&p_z,     g_z);
    cudaGetSymbolAddress((void**)&p_P,     g_P);
    cudaGetSymbolAddress((void**)&p_sw,    g_smallW);
    cudaGetSymbolAddress((void**)&p_gated, g_gated);
    __nv_bfloat16 *p_xh, *p_xl, *p_zh, *p_zl, *p_wqh, *p_wql, *p_wvh, *p_wvl, *p_woh, *p_wol;
    cudaGetSymbolAddress((void**)&p_xh, g_xh);   cudaGetSymbolAddress((void**)&p_xl, g_xl);
    cudaGetSymbolAddress((void**)&p_zh, g_zh);   cudaGetSymbolAddress((void**)&p_zl, g_zl);
    cudaGetSymbolAddress((void**)&p_wqh, g_wqh); cudaGetSymbolAddress((void**)&p_wql, g_wql);
    cudaGetSymbolAddress((void**)&p_wvh, g_wvh); cudaGetSymbolAddress((void**)&p_wvl, g_wvl);
    cudaGetSymbolAddress((void**)&p_woh, g_woh); cudaGetSymbolAddress((void**)&p_wol, g_wol);

    cudaFuncSetAttribute(rw_gemm_mma, cudaFuncAttributeMaxDynamicSharedMemorySize, 65536);
    cudaFuncSetAttribute(rw_attn_mma, cudaFuncAttributeMaxDynamicSharedMemorySize, 98304);

    rw_concat_w<<<(CD * 272 + 255) / 256, 256>>>(w1w, w2w, w1r, w2r, memg_w);
    rw_gemm<<<dim3(5, CBT / 128), 256>>>(x, CD, p_sw, 272, p_P, 272, 272);
    rw_split<<<(CBT * CD + 255) / 256, 256>>>(x, p_xh, p_xl, CBT * CD);
    rw_splitT<<<dim3(QKVLD / 32, CD / 32), dim3(32, 8)>>>(qkv_w, p_wqh, p_wql, QKVLD);
    rw_splitT<<<dim3(CD / 32, CD / 32), dim3(32, 8)>>>(memv_w, p_wvh, p_wvl, CD);
    rw_splitT<<<dim3(CD / 32, CD / 32), dim3(32, 8)>>>(out_w, p_woh, p_wol, CD);
    rw_gemm_mma<<<dim3(QKVLD / 128, CBT / 128), 256, 65536>>>(
        p_xh, p_xl, p_wqh, p_wql, qkv_b, p_qkv, QKVLD, 0, nullptr, nullptr);
    rw_splitqkv<<<(CBT * CD / 2 + 255) / 256, 256>>>();
    rw_attn_mma<<<dim3(CT / 128, NBH), 256, 98304>>>();
    rw_lines<<<(CBT * CH + 255) / 256, 256>>>();
    rw_scanA<<<dim3(NBH, NCH), 128>>>(decay_logits);
    rw_scanB<<<NBH, 64>>>(decay_logits);
    rw_scanC<<<dim3(NBH, NCH), 128>>>(decay_logits, rw_mix);
    rw_gate<<<(CBT + 255) / 256, 256>>>(mem_scale, memg_b);
    rw_gemm_mma<<<dim3(CD / 128, CBT / 128), 256, 65536>>>(
        p_xh, p_xl, p_wvh, p_wvl, memv_b, p_z, CD, 1, p_seq, p_gated);
    rw_split<<<(CBT * CD + 255) / 256, 256>>>(p_z, p_zh, p_zl, CBT * CD);
    rw_gemm_mma<<<dim3(CD / 128, CBT / 128), 256, 65536>>>(
        p_zh, p_zl, p_woh, p_wol, out_b, (float*)d_out, CD, 0, nullptr, nullptr);
}